// round 6
// baseline (speedup 1.0000x reference)
#include <cuda_runtime.h>
#include <cuda_bf16.h>
#include <math.h>
#include <stdint.h>

#define NN 100000
#define EE 1600000
#define EPSV 1e-5f

// ================= device scratch (zero-initialized) =================
__device__ __nv_bfloat16 g_actH[(size_t)NN * 256];   // activation bf16 hi, row stride KP
__device__ __nv_bfloat16 g_actL[(size_t)NN * 256];   // activation bf16 lo
__device__ float g_bufA[(size_t)NN * 224];           // GEMM output fp32, row stride Npad
__device__ __nv_bfloat16 g_hB[57344];                // W^T bf16 hi, [Npad, KP]
__device__ __nv_bfloat16 g_lB[57344];                // W^T bf16 lo
__device__ int   g_deg[NN];
__device__ float g_dis[NN];
__device__ int   g_cnt[NN];
__device__ int   g_rowptr[NN + 1];
__device__ int   g_cursor[NN];
__device__ int   g_blocksum[256];
__device__ int   g_blockoff[256];
__device__ int   g_src[EE];
__device__ float g_w[EE];
__device__ float g_sums[256];
__device__ float g_sumsq[256];
__device__ float g_scale[256];
__device__ float g_shift[256];
__device__ float g_cvec[256];

__device__ __forceinline__ uint32_t smem_u32(const void* p) {
    uint32_t a;
    asm("{ .reg .u64 t; cvta.to.shared.u64 t, %1; cvt.u32.u64 %0, t; }" : "=r"(a) : "l"(p));
    return a;
}

// ================= preprocessing =================
__global__ void k_init() {
    int i = blockIdx.x * blockDim.x + threadIdx.x;
    if (i < NN) g_deg[i] = 1;
}
__global__ void k_hist(const int* __restrict__ dst) {
    int e = blockIdx.x * blockDim.x + threadIdx.x;
    if (e < EE) atomicAdd(&g_deg[dst[e]], 1);
}
__global__ void k_dis() {
    int i = blockIdx.x * blockDim.x + threadIdx.x;
    if (i < NN) {
        int dg = g_deg[i];
        g_dis[i] = rsqrtf((float)dg);
        g_cnt[i] = dg - 1;
    }
}
__global__ void k_scan1() {
    __shared__ int sh[512];
    int i = blockIdx.x * 512 + threadIdx.x;
    int v = (i < NN) ? g_cnt[i] : 0;
    sh[threadIdx.x] = v;
    __syncthreads();
    #pragma unroll
    for (int off = 1; off < 512; off <<= 1) {
        int t = (threadIdx.x >= off) ? sh[threadIdx.x - off] : 0;
        __syncthreads();
        sh[threadIdx.x] += t;
        __syncthreads();
    }
    if (i < NN) g_rowptr[i] = sh[threadIdx.x] - v;
    if (threadIdx.x == 511) g_blocksum[blockIdx.x] = sh[511];
}
__global__ void k_scan2(int nb) {
    __shared__ int sh[256];
    int v = (threadIdx.x < nb) ? g_blocksum[threadIdx.x] : 0;
    sh[threadIdx.x] = v;
    __syncthreads();
    #pragma unroll
    for (int off = 1; off < 256; off <<= 1) {
        int t = (threadIdx.x >= off) ? sh[threadIdx.x - off] : 0;
        __syncthreads();
        sh[threadIdx.x] += t;
        __syncthreads();
    }
    if (threadIdx.x < nb) g_blockoff[threadIdx.x] = sh[threadIdx.x] - v;
}
__global__ void k_scan3() {
    int i = blockIdx.x * 512 + threadIdx.x;
    if (i < NN) {
        int r = g_rowptr[i] + g_blockoff[blockIdx.x];
        g_rowptr[i] = r;
        g_cursor[i] = r;
    }
    if (i == 0 && blockIdx.x == 0) g_rowptr[NN] = EE;
}
__global__ void k_fill(const int* __restrict__ ei) {
    int e = blockIdx.x * blockDim.x + threadIdx.x;
    if (e < EE) {
        int s  = ei[e];
        int dv = ei[EE + e];
        float w = g_dis[s] * g_dis[dv];
        int p = atomicAdd(&g_cursor[dv], 1);
        g_src[p] = s;
        g_w[p]   = w;
    }
}

// ================= conversions / BN folding =================
__global__ void k_convX(const float* __restrict__ x) {
    int i = blockIdx.x;
    int k = threadIdx.x;
    float v = (k < 220) ? x[(size_t)i * 220 + k] : 0.f;
    __nv_bfloat16 hv = __float2bfloat16(v);
    g_actH[(size_t)i * 256 + k] = hv;
    g_actL[(size_t)i * 256 + k] = __float2bfloat16(v - __bfloat162float(hv));
}

__global__ void k_prepW(const float* __restrict__ W, int K_, int N_, int KP, int Npad, int useScale) {
    int idx = blockIdx.x * blockDim.x + threadIdx.x;
    if (idx >= Npad * KP) return;
    int n = idx / KP, k = idx % KP;
    float v = 0.f;
    if (n < N_ && k < K_) {
        v = W[(size_t)k * N_ + n];
        if (useScale) v *= g_scale[k];
    }
    __nv_bfloat16 hv = __float2bfloat16(v);
    g_hB[idx] = hv;
    g_lB[idx] = __float2bfloat16(v - __bfloat162float(hv));
}

__global__ void k_zero_stats() {
    int i = threadIdx.x;
    g_sums[i] = 0.f;
    g_sumsq[i] = 0.f;
}
__global__ void k_finalize(const float* __restrict__ gg, const float* __restrict__ bb, int d) {
    int j = threadIdx.x;
    if (j < d) {
        float m   = g_sums[j] * (1.f / NN);
        float var = g_sumsq[j] * (1.f / NN) - m * m;
        float rs  = rsqrtf(var + EPSV);
        float sc  = rs * gg[j];
        g_scale[j] = sc;
        g_shift[j] = bb[j] - m * sc;
    }
}
__global__ void k_cvec(const float* __restrict__ W, int K_, int N_) {
    int n = threadIdx.x;
    if (n < N_) {
        float s = 0.f;
        for (int k = 0; k < K_; k++) s += g_shift[k] * W[(size_t)k * N_ + n];
        g_cvec[n] = s;
    } else {
        g_cvec[n] = 0.f;
    }
}

// ================= HMMA bf16 3-term split GEMM (N=64 tile, swizzled smem) ========
// D[128 rows, 64 cols per CTA] = (Ah+Al) @ (Bh+Bl)^T, dropping Al*Bl.
// smem rows are 64 bf16 = 128B; 16B chunk q at row r stored at chunk (q ^ (r&7)).
__device__ __forceinline__ void ldsm4(uint32_t& r0, uint32_t& r1, uint32_t& r2, uint32_t& r3,
                                      uint32_t addr) {
    asm volatile("ldmatrix.sync.aligned.m8n8.x4.shared.b16 {%0,%1,%2,%3}, [%4];"
        : "=r"(r0), "=r"(r1), "=r"(r2), "=r"(r3) : "r"(addr));
}
__device__ __forceinline__ void mma16816(float* d, uint32_t a0, uint32_t a1, uint32_t a2,
                                         uint32_t a3, uint32_t b0, uint32_t b1) {
    asm volatile(
        "mma.sync.aligned.m16n8k16.row.col.f32.bf16.bf16.f32 "
        "{%0,%1,%2,%3}, {%4,%5,%6,%7}, {%8,%9}, {%0,%1,%2,%3};"
        : "+f"(d[0]), "+f"(d[1]), "+f"(d[2]), "+f"(d[3])
        : "r"(a0), "r"(a1), "r"(a2), "r"(a3), "r"(b0), "r"(b1));
}
#define SWZ(r, q) (((uint32_t)(r) << 7) + ((((uint32_t)(q)) ^ ((uint32_t)(r) & 7)) << 4))

__global__ void __launch_bounds__(256, 2) k_hgemm(int KP, int Npad, int useCvec) {
    __shared__ __nv_bfloat16 sAh[128 * 64];
    __shared__ __nv_bfloat16 sAl[128 * 64];
    __shared__ __nv_bfloat16 sBh[64 * 64];
    __shared__ __nv_bfloat16 sBl[64 * 64];

    int tid = threadIdx.x;
    int warp = tid >> 5, lane = tid & 31;
    int rowbase = blockIdx.y * 128;
    int colbase = blockIdx.x * 64;
    int navail = Npad - colbase;              // 32 or >=64
    int jm8  = navail >= 64 ? 8 : 4;          // n8-tiles to compute
    int tmax = jm8 >> 1;                      // ldsm pair-tiles

    float acc[8][4];
    #pragma unroll
    for (int j = 0; j < 8; j++)
        #pragma unroll
        for (int q = 0; q < 4; q++) acc[j][q] = 0.f;

    uint32_t sAhB = smem_u32(sAh), sAlB = smem_u32(sAl);
    uint32_t sBhB = smem_u32(sBh), sBlB = smem_u32(sBl);

    // per-lane ldmatrix row indices
    int arow = warp * 16 + (lane & 15);       // A rows
    int achk = lane >> 4;                     // 0/1 -> k chunk within step
    int brow = (lane & 7) + ((lane >> 4) << 3);
    int bchk = (lane >> 3) & 1;

    int nchunks = KP >> 6;
    for (int c = 0; c < nchunks; c++) {
        int k0 = c << 6;
        // A tiles: 128 rows x 64 bf16 hi/lo (1024 uint4 each)
        #pragma unroll
        for (int it = 0; it < 4; it++) {
            int u = tid + it * 256;
            int r = u >> 3, q = u & 7;
            int gr = rowbase + r;
            uint4 vh = make_uint4(0u, 0u, 0u, 0u);
            uint4 vl = vh;
            if (gr < NN) {
                size_t off = (size_t)gr * KP + k0 + q * 8;
                vh = *(const uint4*)(g_actH + off);
                vl = *(const uint4*)(g_actL + off);
            }
            uint32_t dz = SWZ(r, q);
            *(uint4*)((char*)sAh + dz) = vh;
            *(uint4*)((char*)sAl + dz) = vl;
        }
        // B tiles: 64 rows x 64 bf16 hi/lo (512 uint4 each)
        #pragma unroll
        for (int it = 0; it < 2; it++) {
            int u = tid + it * 256;
            int n = u >> 3, q = u & 7;
            uint4 vh = make_uint4(0u, 0u, 0u, 0u);
            uint4 vl = vh;
            if (n < navail) {
                size_t off = (size_t)(colbase + n) * KP + k0 + q * 8;
                vh = *(const uint4*)(g_hB + off);
                vl = *(const uint4*)(g_lB + off);
            }
            uint32_t dz = SWZ(n, q);
            *(uint4*)((char*)sBh + dz) = vh;
            *(uint4*)((char*)sBl + dz) = vl;
        }
        __syncthreads();

        #pragma unroll
        for (int s = 0; s < 4; s++) {
            int aq = s * 2 + achk;
            uint32_t aoff = SWZ(arow, aq);
            uint32_t ah0, ah1, ah2, ah3, al0, al1, al2, al3;
            ldsm4(ah0, ah1, ah2, ah3, sAhB + aoff);
            ldsm4(al0, al1, al2, al3, sAlB + aoff);
            int bq = s * 2 + bchk;
            uint32_t bh[16], bl[16];
            for (int t = 0; t < tmax; t++) {
                uint32_t boff = SWZ(brow + t * 16, bq);
                ldsm4(bh[t*4], bh[t*4+1], bh[t*4+2], bh[t*4+3], sBhB + boff);
                ldsm4(bl[t*4], bl[t*4+1], bl[t*4+2], bl[t*4+3], sBlB + boff);
            }
            for (int j = 0; j < jm8; j++) {
                mma16816(acc[j], ah0, ah1, ah2, ah3, bh[j*2], bh[j*2+1]);
                mma16816(acc[j], ah0, ah1, ah2, ah3, bl[j*2], bl[j*2+1]);
                mma16816(acc[j], al0, al1, al2, al3, bh[j*2], bh[j*2+1]);
            }
        }
        __syncthreads();
    }

    // epilogue: store fp32 + cvec
    int r0 = rowbase + warp * 16 + (lane >> 2);
    int c00 = colbase + (lane & 3) * 2;
    for (int j = 0; j < jm8; j++) {
        int col = c00 + j * 8;
        float cv0 = useCvec ? g_cvec[col] : 0.f;
        float cv1 = useCvec ? g_cvec[col + 1] : 0.f;
        if (r0 < NN) {
            float* p = g_bufA + (size_t)r0 * Npad + col;
            p[0] = acc[j][0] + cv0;
            p[1] = acc[j][1] + cv1;
        }
        if (r0 + 8 < NN) {
            float* p = g_bufA + (size_t)(r0 + 8) * Npad + col;
            p[0] = acc[j][2] + cv0;
            p[1] = acc[j][3] + cv1;
        }
    }
}

// ================= aggregation (+bias, relu, bf16 split-out, fused BN stats / log_softmax) ===
template <int EPG, int CPT, bool LAST>
__global__ void __launch_bounds__(256) k_agg(const float* __restrict__ bias,
                                             float* __restrict__ outp,
                                             int d, int s4, int KPn)
{
    constexpr int G = 32 / EPG;
    int lane = threadIdx.x & 31;
    int warp = threadIdx.x >> 5;
    int sub  = lane & (G - 1);
    int grp  = lane / G;

    __shared__ float sh_sum[256], sh_sq[256];
    if (!LAST) {
        if (threadIdx.x < 256) { sh_sum[threadIdx.x] = 0.f; sh_sq[threadIdx.x] = 0.f; }
        __syncthreads();
    }

    float st_s[CPT * 4], st_q[CPT * 4];
    #pragma unroll
    for (int i = 0; i < CPT * 4; i++) { st_s[i] = 0.f; st_q[i] = 0.f; }

    const float4* __restrict__ H = (const float4*)g_bufA;
    const __nv_bfloat16 bz = __float2bfloat16(0.f);

    for (int node = blockIdx.x * 8 + warp; node < NN; node += gridDim.x * 8) {
        float4 acc[CPT];
        #pragma unroll
        for (int c = 0; c < CPT; c++) acc[c] = make_float4(0.f, 0.f, 0.f, 0.f);

        float dn = g_dis[node];
        if (grp == 0) {
            float sw = dn * dn;
            #pragma unroll
            for (int c = 0; c < CPT; c++) {
                int j = sub + c * G;
                if (j < s4) {
                    float4 h = H[(size_t)node * s4 + j];
                    acc[c].x = sw * h.x; acc[c].y = sw * h.y;
                    acc[c].z = sw * h.z; acc[c].w = sw * h.w;
                }
            }
        }

        int start = g_rowptr[node], end = g_rowptr[node + 1];
        for (int base = start; base < end; base += 32) {
            int e = base + lane;
            int ssrc = 0; float ww = 0.f;
            if (e < end) { ssrc = g_src[e]; ww = g_w[e]; }
            int cnt = min(32, end - base);
            int steps = (cnt + EPG - 1) / EPG;
            for (int t = 0; t < steps; t++) {
                int ei = t * EPG + grp;
                int   s2 = __shfl_sync(0xffffffffu, ssrc, ei);
                float w2 = __shfl_sync(0xffffffffu, ww, ei);
                const float4* hr = H + (size_t)s2 * s4;
                #pragma unroll
                for (int c = 0; c < CPT; c++) {
                    int j = sub + c * G;
                    if (j < s4) {
                        float4 h = hr[j];
                        acc[c].x += w2 * h.x; acc[c].y += w2 * h.y;
                        acc[c].z += w2 * h.z; acc[c].w += w2 * h.w;
                    }
                }
            }
        }

        if (EPG > 1) {
            #pragma unroll
            for (int off = G; off < 32; off <<= 1) {
                #pragma unroll
                for (int c = 0; c < CPT; c++) {
                    acc[c].x += __shfl_xor_sync(0xffffffffu, acc[c].x, off);
                    acc[c].y += __shfl_xor_sync(0xffffffffu, acc[c].y, off);
                    acc[c].z += __shfl_xor_sync(0xffffffffu, acc[c].z, off);
                    acc[c].w += __shfl_xor_sync(0xffffffffu, acc[c].w, off);
                }
            }
        }

        if (!LAST) {
            if (grp == 0) {
                #pragma unroll
                for (int c = 0; c < CPT; c++) {
                    int j = sub + c * G;
                    float vals[4] = {acc[c].x, acc[c].y, acc[c].z, acc[c].w};
                    #pragma unroll
                    for (int q = 0; q < 4; q++) {
                        int col = j * 4 + q;
                        if (col < d) {
                            float v = fmaxf(vals[q] + bias[col], 0.f);
                            __nv_bfloat16 hv = __float2bfloat16(v);
                            g_actH[(size_t)node * KPn + col] = hv;
                            g_actL[(size_t)node * KPn + col] =
                                __float2bfloat16(v - __bfloat162float(hv));
                            st_s[c * 4 + q] += v;
                            st_q[c * 4 + q] += v * v;
                        }
                    }
                }
                for (int col = d + sub; col < KPn; col += G) {
                    g_actH[(size_t)node * KPn + col] = bz;
                    g_actL[(size_t)node * KPn + col] = bz;
                }
            }
        } else {
            int j = sub;
            float vals[4] = {acc[0].x, acc[0].y, acc[0].z, acc[0].w};
            float lmax = -INFINITY;
            #pragma unroll
            for (int q = 0; q < 4; q++) {
                int col = j * 4 + q;
                float v = (grp == 0 && col < d) ? vals[q] + bias[col] : -INFINITY;
                vals[q] = v;
                lmax = fmaxf(lmax, v);
            }
            #pragma unroll
            for (int off = 1; off < G; off <<= 1)
                lmax = fmaxf(lmax, __shfl_xor_sync(0xffffffffu, lmax, off));
            float lsum = 0.f;
            #pragma unroll
            for (int q = 0; q < 4; q++) {
                int col = j * 4 + q;
                if (grp == 0 && col < d) lsum += expf(vals[q] - lmax);
            }
            #pragma unroll
            for (int off = 1; off < G; off <<= 1)
                lsum += __shfl_xor_sync(0xffffffffu, lsum, off);
            float lse = logf(lsum) + lmax;
            if (grp == 0) {
                #pragma unroll
                for (int q = 0; q < 4; q++) {
                    int col = j * 4 + q;
                    if (col < d) outp[(size_t)node * d + col] = vals[q] - lse;
                }
            }
        }
    }

    if (!LAST) {
        __syncthreads();
        if (grp == 0) {
            #pragma unroll
            for (int c = 0; c < CPT; c++) {
                int j = sub + c * G;
                #pragma unroll
                for (int q = 0; q < 4; q++) {
                    int col = j * 4 + q;
                    if (col < d) {
                        atomicAdd(&sh_sum[col], st_s[c * 4 + q]);
                        atomicAdd(&sh_sq[col],  st_q[c * 4 + q]);
                    }
                }
            }
        }
        __syncthreads();
        if (threadIdx.x < d) {
            atomicAdd(&g_sums[threadIdx.x],  sh_sum[threadIdx.x]);
            atomicAdd(&g_sumsq[threadIdx.x], sh_sq[threadIdx.x]);
        }
    }
}

// ================= launch =================
extern "C" void kernel_launch(void* const* d_in, const int* in_sizes, int n_in,
                              void* d_out, int out_size) {
    const float* x  = (const float*)d_in[0];
    const int*   ei = (const int*)d_in[1];
    static const int DIMS_[7] = {220, 220, 150, 100, 60, 30, 17};
    static const int KPt[6]   = {256, 256, 192, 128, 64, 64};   // K stride (bf16 buffers)
    static const int NPADt[6] = {224, 160, 128, 64, 32, 32};    // output cols padded
    const float* W[6]; const float* b[6];
    for (int i = 0; i < 6; i++) {
        W[i] = (const float*)d_in[2 + 2 * i];
        b[i] = (const float*)d_in[3 + 2 * i];
    }
    const float* gpar[5]; const float* bpar[5];
    for (int i = 0; i < 5; i++) {
        gpar[i] = (const float*)d_in[14 + 2 * i];
        bpar[i] = (const float*)d_in[15 + 2 * i];
    }

    // preprocessing
    k_init<<<(NN + 255) / 256, 256>>>();
    k_hist<<<(EE + 255) / 256, 256>>>(ei + EE);
    k_dis<<<(NN + 255) / 256, 256>>>();
    int nb = (NN + 511) / 512;
    k_scan1<<<nb, 512>>>();
    k_scan2<<<1, 256>>>(nb);
    k_scan3<<<nb, 512>>>();
    k_fill<<<(EE + 255) / 256, 256>>>(ei);
    k_convX<<<NN, 256>>>(x);

    const int AGG_GRID = 1184;
    const int ROW_BLKS = (NN + 127) / 128;   // 782

    for (int L = 0; L < 6; L++) {
        int K_ = DIMS_[L], Nc = DIMS_[L + 1];
        int KP = KPt[L], Npad = NPADt[L];

        if (L > 0) {
            k_finalize<<<1, 256>>>(gpar[L - 1], bpar[L - 1], K_);
            k_cvec<<<1, 256>>>(W[L], K_, Nc);
        }
        k_prepW<<<(Npad * KP + 255) / 256, 256>>>(W[L], K_, Nc, KP, Npad, L > 0 ? 1 : 0);

        dim3 gg((Npad + 63) / 64, ROW_BLKS);
        k_hgemm<<<gg, 256>>>(KP, Npad, L > 0 ? 1 : 0);

        if (L < 5) {
            k_zero_stats<<<1, 256>>>();
            int s4 = Npad / 4;
            int KPn = KPt[L + 1];
            if (L <= 1)      k_agg<1, 2, false><<<AGG_GRID, 256>>>(b[L], nullptr, Nc, s4, KPn);
            else if (L == 2) k_agg<1, 1, false><<<AGG_GRID, 256>>>(b[L], nullptr, Nc, s4, KPn);
            else if (L == 3) k_agg<2, 1, false><<<AGG_GRID, 256>>>(b[L], nullptr, Nc, s4, KPn);
            else             k_agg<4, 1, false><<<AGG_GRID, 256>>>(b[L], nullptr, Nc, s4, KPn);
        } else {
            k_agg<4, 1, true><<<AGG_GRID, 256>>>(b[L], (float*)d_out, Nc, Npad / 4, 0);
        }
    }
}

// round 7
// speedup vs baseline: 1.7928x; 1.7928x over previous
#include <cuda_runtime.h>
#include <cuda_bf16.h>
#include <math.h>
#include <stdint.h>

#define NN 100000
#define EE 1600000
#define EPSV 1e-5f

// ================= device scratch (zero-initialized) =================
__device__ __nv_bfloat16 g_actH[(size_t)NN * 256];   // activation bf16 hi, row stride KP
__device__ __nv_bfloat16 g_actL[(size_t)NN * 256];   // activation bf16 lo
__device__ float g_bufA[(size_t)NN * 224];           // GEMM output fp32, row stride Npad
__device__ __nv_bfloat16 g_hB[57344];                // W^T bf16 hi, [Npad, KP]
__device__ __nv_bfloat16 g_lB[57344];                // W^T bf16 lo
__device__ int   g_deg[NN];
__device__ float g_dis[NN];
__device__ int   g_cnt[NN];
__device__ int   g_rowptr[NN + 1];
__device__ int   g_cursor[NN];
__device__ int   g_blocksum[256];
__device__ int   g_blockoff[256];
__device__ int   g_src[EE];
__device__ float g_w[EE];
__device__ float g_sums[256];
__device__ float g_sumsq[256];
__device__ float g_scale[256];
__device__ float g_shift[256];
__device__ float g_cvec[256];

__device__ __forceinline__ uint32_t smem_u32(const void* p) {
    uint32_t a;
    asm("{ .reg .u64 t; cvta.to.shared.u64 t, %1; cvt.u32.u64 %0, t; }" : "=r"(a) : "l"(p));
    return a;
}

// ================= preprocessing =================
__global__ void k_init() {
    int i = blockIdx.x * blockDim.x + threadIdx.x;
    if (i < NN) g_deg[i] = 1;
}
__global__ void k_hist(const int* __restrict__ dst) {
    int e = blockIdx.x * blockDim.x + threadIdx.x;
    if (e < EE) atomicAdd(&g_deg[dst[e]], 1);
}
__global__ void k_dis() {
    int i = blockIdx.x * blockDim.x + threadIdx.x;
    if (i < NN) {
        int dg = g_deg[i];
        g_dis[i] = rsqrtf((float)dg);
        g_cnt[i] = dg - 1;
    }
}
__global__ void k_scan1() {
    __shared__ int sh[512];
    int i = blockIdx.x * 512 + threadIdx.x;
    int v = (i < NN) ? g_cnt[i] : 0;
    sh[threadIdx.x] = v;
    __syncthreads();
    #pragma unroll
    for (int off = 1; off < 512; off <<= 1) {
        int t = (threadIdx.x >= off) ? sh[threadIdx.x - off] : 0;
        __syncthreads();
        sh[threadIdx.x] += t;
        __syncthreads();
    }
    if (i < NN) g_rowptr[i] = sh[threadIdx.x] - v;
    if (threadIdx.x == 511) g_blocksum[blockIdx.x] = sh[511];
}
__global__ void k_scan2(int nb) {
    __shared__ int sh[256];
    int v = (threadIdx.x < nb) ? g_blocksum[threadIdx.x] : 0;
    sh[threadIdx.x] = v;
    __syncthreads();
    #pragma unroll
    for (int off = 1; off < 256; off <<= 1) {
        int t = (threadIdx.x >= off) ? sh[threadIdx.x - off] : 0;
        __syncthreads();
        sh[threadIdx.x] += t;
        __syncthreads();
    }
    if (threadIdx.x < nb) g_blockoff[threadIdx.x] = sh[threadIdx.x] - v;
}
__global__ void k_scan3() {
    int i = blockIdx.x * 512 + threadIdx.x;
    if (i < NN) {
        int r = g_rowptr[i] + g_blockoff[blockIdx.x];
        g_rowptr[i] = r;
        g_cursor[i] = r;
    }
    if (i == 0 && blockIdx.x == 0) g_rowptr[NN] = EE;
}
__global__ void k_fill(const int* __restrict__ ei) {
    int e = blockIdx.x * blockDim.x + threadIdx.x;
    if (e < EE) {
        int s  = ei[e];
        int dv = ei[EE + e];
        float w = g_dis[s] * g_dis[dv];
        int p = atomicAdd(&g_cursor[dv], 1);
        g_src[p] = s;
        g_w[p]   = w;
    }
}

// ================= conversions / BN folding =================
__global__ void k_convX(const float* __restrict__ x) {
    int i = blockIdx.x;
    int k = threadIdx.x;
    float v = (k < 220) ? x[(size_t)i * 220 + k] : 0.f;
    __nv_bfloat16 hv = __float2bfloat16(v);
    g_actH[(size_t)i * 256 + k] = hv;
    g_actL[(size_t)i * 256 + k] = __float2bfloat16(v - __bfloat162float(hv));
}

__global__ void k_prepW(const float* __restrict__ W, int K_, int N_, int KP, int Npad, int useScale) {
    int idx = blockIdx.x * blockDim.x + threadIdx.x;
    if (idx >= Npad * KP) return;
    int n = idx / KP, k = idx % KP;
    float v = 0.f;
    if (n < N_ && k < K_) {
        v = W[(size_t)k * N_ + n];
        if (useScale) v *= g_scale[k];
    }
    __nv_bfloat16 hv = __float2bfloat16(v);
    g_hB[idx] = hv;
    g_lB[idx] = __float2bfloat16(v - __bfloat162float(hv));
}

__global__ void k_zero_stats() {
    int i = threadIdx.x;
    g_sums[i] = 0.f;
    g_sumsq[i] = 0.f;
}
__global__ void k_finalize(const float* __restrict__ gg, const float* __restrict__ bb, int d) {
    int j = threadIdx.x;
    if (j < d) {
        float m   = g_sums[j] * (1.f / NN);
        float var = g_sumsq[j] * (1.f / NN) - m * m;
        float rs  = rsqrtf(var + EPSV);
        float sc  = rs * gg[j];
        g_scale[j] = sc;
        g_shift[j] = bb[j] - m * sc;
    }
}
__global__ void k_cvec(const float* __restrict__ W, int K_, int N_) {
    int n = threadIdx.x;
    if (n < N_) {
        float s = 0.f;
        for (int k = 0; k < K_; k++) s += g_shift[k] * W[(size_t)k * N_ + n];
        g_cvec[n] = s;
    } else {
        g_cvec[n] = 0.f;
    }
}

// ================= HMMA bf16 3-term split GEMM (templated N tile) ========
// D[128 rows, JM8*8 cols per CTA] = (Ah+Al) @ (Bh+Bl)^T, dropping Al*Bl.
// smem rows are 64 bf16 = 128B; 16B chunk q at row r stored at chunk (q ^ (r&7)).
__device__ __forceinline__ void ldsm4(uint32_t& r0, uint32_t& r1, uint32_t& r2, uint32_t& r3,
                                      uint32_t addr) {
    asm volatile("ldmatrix.sync.aligned.m8n8.x4.shared.b16 {%0,%1,%2,%3}, [%4];"
        : "=r"(r0), "=r"(r1), "=r"(r2), "=r"(r3) : "r"(addr));
}
__device__ __forceinline__ void mma16816(float* d, uint32_t a0, uint32_t a1, uint32_t a2,
                                         uint32_t a3, uint32_t b0, uint32_t b1) {
    asm volatile(
        "mma.sync.aligned.m16n8k16.row.col.f32.bf16.bf16.f32 "
        "{%0,%1,%2,%3}, {%4,%5,%6,%7}, {%8,%9}, {%0,%1,%2,%3};"
        : "+f"(d[0]), "+f"(d[1]), "+f"(d[2]), "+f"(d[3])
        : "r"(a0), "r"(a1), "r"(a2), "r"(a3), "r"(b0), "r"(b1));
}
#define SWZ(r, q) (((uint32_t)(r) << 7) + ((((uint32_t)(q)) ^ ((uint32_t)(r) & 7)) << 4))

template <int JM8>
__global__ void __launch_bounds__(256, 2) k_hgemm(int KP, int Npad, int useCvec, int colOff) {
    constexpr int TMAX  = JM8 / 2;     // 16-row B ldsm tiles
    constexpr int BROWS = JM8 * 8;     // B rows in this tile (32 or 64)
    __shared__ __nv_bfloat16 sAh[128 * 64];
    __shared__ __nv_bfloat16 sAl[128 * 64];
    __shared__ __nv_bfloat16 sBh[64 * 64];
    __shared__ __nv_bfloat16 sBl[64 * 64];

    int tid = threadIdx.x;
    int warp = tid >> 5, lane = tid & 31;
    int rowbase = blockIdx.y * 128;
    int colbase = colOff + blockIdx.x * 64;

    float acc[JM8][4];
    #pragma unroll
    for (int j = 0; j < JM8; j++)
        #pragma unroll
        for (int q = 0; q < 4; q++) acc[j][q] = 0.f;

    uint32_t sAhB = smem_u32(sAh), sAlB = smem_u32(sAl);
    uint32_t sBhB = smem_u32(sBh), sBlB = smem_u32(sBl);

    int arow = warp * 16 + (lane & 15);
    int achk = lane >> 4;
    int brow = (lane & 7) + ((lane >> 4) << 3);
    int bchk = (lane >> 3) & 1;

    int nchunks = KP >> 6;
    for (int c = 0; c < nchunks; c++) {
        int k0 = c << 6;
        // A tiles: 128 rows x 64 bf16 hi/lo
        #pragma unroll
        for (int it = 0; it < 4; it++) {
            int u = tid + it * 256;
            int r = u >> 3, q = u & 7;
            int gr = rowbase + r;
            uint4 vh = make_uint4(0u, 0u, 0u, 0u);
            uint4 vl = vh;
            if (gr < NN) {
                size_t off = (size_t)gr * KP + k0 + q * 8;
                vh = *(const uint4*)(g_actH + off);
                vl = *(const uint4*)(g_actL + off);
            }
            uint32_t dz = SWZ(r, q);
            *(uint4*)((char*)sAh + dz) = vh;
            *(uint4*)((char*)sAl + dz) = vl;
        }
        // B tiles: BROWS rows x 64 bf16 hi/lo (rows guaranteed in-range by launch math)
        #pragma unroll
        for (int it = 0; it < BROWS / 32; it++) {
            int u = tid + it * 256;
            int n = u >> 3, q = u & 7;
            size_t off = (size_t)(colbase + n) * KP + k0 + q * 8;
            uint32_t dz = SWZ(n, q);
            *(uint4*)((char*)sBh + dz) = *(const uint4*)(g_hB + off);
            *(uint4*)((char*)sBl + dz) = *(const uint4*)(g_lB + off);
        }
        __syncthreads();

        #pragma unroll
        for (int s = 0; s < 4; s++) {
            int aq = s * 2 + achk;
            uint32_t aoff = SWZ(arow, aq);
            uint32_t ah0, ah1, ah2, ah3, al0, al1, al2, al3;
            ldsm4(ah0, ah1, ah2, ah3, sAhB + aoff);
            ldsm4(al0, al1, al2, al3, sAlB + aoff);
            int bq = s * 2 + bchk;
            uint32_t bh[JM8 * 2], bl[JM8 * 2];
            #pragma unroll
            for (int t = 0; t < TMAX; t++) {
                uint32_t boff = SWZ(brow + t * 16, bq);
                ldsm4(bh[t*4], bh[t*4+1], bh[t*4+2], bh[t*4+3], sBhB + boff);
                ldsm4(bl[t*4], bl[t*4+1], bl[t*4+2], bl[t*4+3], sBlB + boff);
            }
            #pragma unroll
            for (int j = 0; j < JM8; j++) {
                mma16816(acc[j], ah0, ah1, ah2, ah3, bh[j*2], bh[j*2+1]);
                mma16816(acc[j], ah0, ah1, ah2, ah3, bl[j*2], bl[j*2+1]);
                mma16816(acc[j], al0, al1, al2, al3, bh[j*2], bh[j*2+1]);
            }
        }
        __syncthreads();
    }

    // epilogue: store fp32 + cvec
    int r0 = rowbase + warp * 16 + (lane >> 2);
    int c00 = colbase + (lane & 3) * 2;
    #pragma unroll
    for (int j = 0; j < JM8; j++) {
        int col = c00 + j * 8;
        float cv0 = useCvec ? g_cvec[col] : 0.f;
        float cv1 = useCvec ? g_cvec[col + 1] : 0.f;
        if (r0 < NN) {
            float* p = g_bufA + (size_t)r0 * Npad + col;
            p[0] = acc[j][0] + cv0;
            p[1] = acc[j][1] + cv1;
        }
        if (r0 + 8 < NN) {
            float* p = g_bufA + (size_t)(r0 + 8) * Npad + col;
            p[0] = acc[j][2] + cv0;
            p[1] = acc[j][3] + cv1;
        }
    }
}

// ================= aggregation (+bias, relu, bf16 split-out, fused BN stats / log_softmax) ===
template <int EPG, int CPT, bool LAST>
__global__ void __launch_bounds__(256) k_agg(const float* __restrict__ bias,
                                             float* __restrict__ outp,
                                             int d, int s4, int KPn)
{
    constexpr int G = 32 / EPG;
    int lane = threadIdx.x & 31;
    int warp = threadIdx.x >> 5;
    int sub  = lane & (G - 1);
    int grp  = lane / G;

    __shared__ float sh_sum[256], sh_sq[256];
    if (!LAST) {
        if (threadIdx.x < 256) { sh_sum[threadIdx.x] = 0.f; sh_sq[threadIdx.x] = 0.f; }
        __syncthreads();
    }

    float st_s[CPT * 4], st_q[CPT * 4];
    #pragma unroll
    for (int i = 0; i < CPT * 4; i++) { st_s[i] = 0.f; st_q[i] = 0.f; }

    const float4* __restrict__ H = (const float4*)g_bufA;
    const __nv_bfloat16 bz = __float2bfloat16(0.f);

    for (int node = blockIdx.x * 8 + warp; node < NN; node += gridDim.x * 8) {
        float4 acc[CPT];
        #pragma unroll
        for (int c = 0; c < CPT; c++) acc[c] = make_float4(0.f, 0.f, 0.f, 0.f);

        float dn = g_dis[node];
        if (grp == 0) {
            float sw = dn * dn;
            #pragma unroll
            for (int c = 0; c < CPT; c++) {
                int j = sub + c * G;
                if (j < s4) {
                    float4 h = H[(size_t)node * s4 + j];
                    acc[c].x = sw * h.x; acc[c].y = sw * h.y;
                    acc[c].z = sw * h.z; acc[c].w = sw * h.w;
                }
            }
        }

        int start = g_rowptr[node], end = g_rowptr[node + 1];
        for (int base = start; base < end; base += 32) {
            int e = base + lane;
            int ssrc = 0; float ww = 0.f;
            if (e < end) { ssrc = g_src[e]; ww = g_w[e]; }
            int cnt = min(32, end - base);
            int steps = (cnt + EPG - 1) / EPG;
            for (int t = 0; t < steps; t++) {
                int ei = t * EPG + grp;
                int   s2 = __shfl_sync(0xffffffffu, ssrc, ei);
                float w2 = __shfl_sync(0xffffffffu, ww, ei);
                const float4* hr = H + (size_t)s2 * s4;
                #pragma unroll
                for (int c = 0; c < CPT; c++) {
                    int j = sub + c * G;
                    if (j < s4) {
                        float4 h = hr[j];
                        acc[c].x += w2 * h.x; acc[c].y += w2 * h.y;
                        acc[c].z += w2 * h.z; acc[c].w += w2 * h.w;
                    }
                }
            }
        }

        if (EPG > 1) {
            #pragma unroll
            for (int off = G; off < 32; off <<= 1) {
                #pragma unroll
                for (int c = 0; c < CPT; c++) {
                    acc[c].x += __shfl_xor_sync(0xffffffffu, acc[c].x, off);
                    acc[c].y += __shfl_xor_sync(0xffffffffu, acc[c].y, off);
                    acc[c].z += __shfl_xor_sync(0xffffffffu, acc[c].z, off);
                    acc[c].w += __shfl_xor_sync(0xffffffffu, acc[c].w, off);
                }
            }
        }

        if (!LAST) {
            if (grp == 0) {
                #pragma unroll
                for (int c = 0; c < CPT; c++) {
                    int j = sub + c * G;
                    float vals[4] = {acc[c].x, acc[c].y, acc[c].z, acc[c].w};
                    #pragma unroll
                    for (int q = 0; q < 4; q++) {
                        int col = j * 4 + q;
                        if (col < d) {
                            float v = fmaxf(vals[q] + bias[col], 0.f);
                            __nv_bfloat16 hv = __float2bfloat16(v);
                            g_actH[(size_t)node * KPn + col] = hv;
                            g_actL[(size_t)node * KPn + col] =
                                __float2bfloat16(v - __bfloat162float(hv));
                            st_s[c * 4 + q] += v;
                            st_q[c * 4 + q] += v * v;
                        }
                    }
                }
                for (int col = d + sub; col < KPn; col += G) {
                    g_actH[(size_t)node * KPn + col] = bz;
                    g_actL[(size_t)node * KPn + col] = bz;
                }
            }
        } else {
            int j = sub;
            float vals[4] = {acc[0].x, acc[0].y, acc[0].z, acc[0].w};
            float lmax = -INFINITY;
            #pragma unroll
            for (int q = 0; q < 4; q++) {
                int col = j * 4 + q;
                float v = (grp == 0 && col < d) ? vals[q] + bias[col] : -INFINITY;
                vals[q] = v;
                lmax = fmaxf(lmax, v);
            }
            #pragma unroll
            for (int off = 1; off < G; off <<= 1)
                lmax = fmaxf(lmax, __shfl_xor_sync(0xffffffffu, lmax, off));
            float lsum = 0.f;
            #pragma unroll
            for (int q = 0; q < 4; q++) {
                int col = j * 4 + q;
                if (grp == 0 && col < d) lsum += expf(vals[q] - lmax);
            }
            #pragma unroll
            for (int off = 1; off < G; off <<= 1)
                lsum += __shfl_xor_sync(0xffffffffu, lsum, off);
            float lse = logf(lsum) + lmax;
            if (grp == 0) {
                #pragma unroll
                for (int q = 0; q < 4; q++) {
                    int col = j * 4 + q;
                    if (col < d) outp[(size_t)node * d + col] = vals[q] - lse;
                }
            }
        }
    }

    if (!LAST) {
        __syncthreads();
        if (grp == 0) {
            #pragma unroll
            for (int c = 0; c < CPT; c++) {
                int j = sub + c * G;
                #pragma unroll
                for (int q = 0; q < 4; q++) {
                    int col = j * 4 + q;
                    if (col < d) {
                        atomicAdd(&sh_sum[col], st_s[c * 4 + q]);
                        atomicAdd(&sh_sq[col],  st_q[c * 4 + q]);
                    }
                }
            }
        }
        __syncthreads();
        if (threadIdx.x < d) {
            atomicAdd(&g_sums[threadIdx.x],  sh_sum[threadIdx.x]);
            atomicAdd(&g_sumsq[threadIdx.x], sh_sq[threadIdx.x]);
        }
    }
}

// ================= launch =================
extern "C" void kernel_launch(void* const* d_in, const int* in_sizes, int n_in,
                              void* d_out, int out_size) {
    const float* x  = (const float*)d_in[0];
    const int*   ei = (const int*)d_in[1];
    static const int DIMS_[7] = {220, 220, 150, 100, 60, 30, 17};
    static const int KPt[6]   = {256, 256, 192, 128, 64, 64};   // K stride (bf16 buffers)
    static const int NPADt[6] = {224, 160, 128, 64, 32, 32};    // output cols padded
    const float* W[6]; const float* b[6];
    for (int i = 0; i < 6; i++) {
        W[i] = (const float*)d_in[2 + 2 * i];
        b[i] = (const float*)d_in[3 + 2 * i];
    }
    const float* gpar[5]; const float* bpar[5];
    for (int i = 0; i < 5; i++) {
        gpar[i] = (const float*)d_in[14 + 2 * i];
        bpar[i] = (const float*)d_in[15 + 2 * i];
    }

    // preprocessing
    k_init<<<(NN + 255) / 256, 256>>>();
    k_hist<<<(EE + 255) / 256, 256>>>(ei + EE);
    k_dis<<<(NN + 255) / 256, 256>>>();
    int nb = (NN + 511) / 512;
    k_scan1<<<nb, 512>>>();
    k_scan2<<<1, 256>>>(nb);
    k_scan3<<<nb, 512>>>();
    k_fill<<<(EE + 255) / 256, 256>>>(ei);
    k_convX<<<NN, 256>>>(x);

    const int AGG_GRID = 1184;
    const int ROW_BLKS = (NN + 127) / 128;   // 782

    for (int L = 0; L < 6; L++) {
        int K_ = DIMS_[L], Nc = DIMS_[L + 1];
        int KP = KPt[L], Npad = NPADt[L];

        if (L > 0) {
            k_finalize<<<1, 256>>>(gpar[L - 1], bpar[L - 1], K_);
            k_cvec<<<1, 256>>>(W[L], K_, Nc);
        }
        k_prepW<<<(Npad * KP + 255) / 256, 256>>>(W[L], K_, Nc, KP, Npad, L > 0 ? 1 : 0);

        int nfull = Npad / 64;               // full 64-col blocks
        int tail  = Npad - nfull * 64;       // 0 or 32
        int uc = L > 0 ? 1 : 0;
        if (nfull > 0) {
            dim3 gg(nfull, ROW_BLKS);
            k_hgemm<8><<<gg, 256>>>(KP, Npad, uc, 0);
        }
        if (tail > 0) {
            dim3 gg(1, ROW_BLKS);
            k_hgemm<4><<<gg, 256>>>(KP, Npad, uc, nfull * 64);
        }

        if (L < 5) {
            k_zero_stats<<<1, 256>>>();
            int s4 = Npad / 4;
            int KPn = KPt[L + 1];
            if (L <= 1)      k_agg<1, 2, false><<<AGG_GRID, 256>>>(b[L], nullptr, Nc, s4, KPn);
            else if (L == 2) k_agg<1, 1, false><<<AGG_GRID, 256>>>(b[L], nullptr, Nc, s4, KPn);
            else if (L == 3) k_agg<2, 1, false><<<AGG_GRID, 256>>>(b[L], nullptr, Nc, s4, KPn);
            else             k_agg<4, 1, false><<<AGG_GRID, 256>>>(b[L], nullptr, Nc, s4, KPn);
        } else {
            k_agg<4, 1, true><<<AGG_GRID, 256>>>(b[L], (float*)d_out, Nc, Npad / 4, 0);
        }
    }
}

// round 8
// speedup vs baseline: 1.8285x; 1.0199x over previous
#include <cuda_runtime.h>
#include <cuda_bf16.h>
#include <cuda_fp16.h>
#include <math.h>
#include <stdint.h>

#define NN 100000
#define EE 1600000
#define EPSV 1e-5f

// ================= device scratch (zero-initialized) =================
__device__ __nv_bfloat16 g_actH[(size_t)NN * 256];   // activation bf16 hi, row stride KP
__device__ __nv_bfloat16 g_actL[(size_t)NN * 256];   // activation bf16 lo
__device__ __half g_bufH[(size_t)NN * 224];          // GEMM output fp16 (layers 1-5), tight stride
__device__ float  g_bufA[(size_t)NN * 20];           // GEMM output fp32 (layer 6), stride 20
__device__ __nv_bfloat16 g_hB[57344];                // W^T bf16 hi, [Npad, KP]
__device__ __nv_bfloat16 g_lB[57344];                // W^T bf16 lo
__device__ int   g_deg[NN];
__device__ float g_dis[NN];
__device__ int   g_cnt[NN];
__device__ int   g_rowptr[NN + 1];
__device__ int   g_cursor[NN];
__device__ int   g_blocksum[256];
__device__ int   g_blockoff[256];
__device__ int   g_src[EE];
__device__ float g_w[EE];
__device__ float g_sums[256];
__device__ float g_sumsq[256];
__device__ float g_scale[256];
__device__ float g_shift[256];
__device__ float g_cvec[256];

__device__ __forceinline__ uint32_t smem_u32(const void* p) {
    uint32_t a;
    asm("{ .reg .u64 t; cvta.to.shared.u64 t, %1; cvt.u32.u64 %0, t; }" : "=r"(a) : "l"(p));
    return a;
}

// ================= preprocessing =================
__global__ void k_init() {
    int i = blockIdx.x * blockDim.x + threadIdx.x;
    if (i < NN) g_deg[i] = 1;
}
__global__ void k_hist(const int* __restrict__ dst) {
    int e = blockIdx.x * blockDim.x + threadIdx.x;
    if (e < EE) atomicAdd(&g_deg[dst[e]], 1);
}
__global__ void k_dis() {
    int i = blockIdx.x * blockDim.x + threadIdx.x;
    if (i < NN) {
        int dg = g_deg[i];
        g_dis[i] = rsqrtf((float)dg);
        g_cnt[i] = dg - 1;
    }
}
__global__ void k_scan1() {
    __shared__ int sh[512];
    int i = blockIdx.x * 512 + threadIdx.x;
    int v = (i < NN) ? g_cnt[i] : 0;
    sh[threadIdx.x] = v;
    __syncthreads();
    #pragma unroll
    for (int off = 1; off < 512; off <<= 1) {
        int t = (threadIdx.x >= off) ? sh[threadIdx.x - off] : 0;
        __syncthreads();
        sh[threadIdx.x] += t;
        __syncthreads();
    }
    if (i < NN) g_rowptr[i] = sh[threadIdx.x] - v;
    if (threadIdx.x == 511) g_blocksum[blockIdx.x] = sh[511];
}
__global__ void k_scan2(int nb) {
    __shared__ int sh[256];
    int v = (threadIdx.x < nb) ? g_blocksum[threadIdx.x] : 0;
    sh[threadIdx.x] = v;
    __syncthreads();
    #pragma unroll
    for (int off = 1; off < 256; off <<= 1) {
        int t = (threadIdx.x >= off) ? sh[threadIdx.x - off] : 0;
        __syncthreads();
        sh[threadIdx.x] += t;
        __syncthreads();
    }
    if (threadIdx.x < nb) g_blockoff[threadIdx.x] = sh[threadIdx.x] - v;
}
__global__ void k_scan3() {
    int i = blockIdx.x * 512 + threadIdx.x;
    if (i < NN) {
        int r = g_rowptr[i] + g_blockoff[blockIdx.x];
        g_rowptr[i] = r;
        g_cursor[i] = r;
    }
    if (i == 0 && blockIdx.x == 0) g_rowptr[NN] = EE;
}
__global__ void k_fill(const int* __restrict__ ei) {
    int e = blockIdx.x * blockDim.x + threadIdx.x;
    if (e < EE) {
        int s  = ei[e];
        int dv = ei[EE + e];
        float w = g_dis[s] * g_dis[dv];
        int p = atomicAdd(&g_cursor[dv], 1);
        g_src[p] = s;
        g_w[p]   = w;
    }
}

// ================= conversions / BN folding =================
__global__ void k_convX(const float* __restrict__ x) {
    int i = blockIdx.x;
    int k = threadIdx.x;
    float v = (k < 220) ? x[(size_t)i * 220 + k] : 0.f;
    __nv_bfloat16 hv = __float2bfloat16(v);
    g_actH[(size_t)i * 256 + k] = hv;
    g_actL[(size_t)i * 256 + k] = __float2bfloat16(v - __bfloat162float(hv));
}

__global__ void k_prepW(const float* __restrict__ W, int K_, int N_, int KP, int Npad, int useScale) {
    int idx = blockIdx.x * blockDim.x + threadIdx.x;
    if (idx >= Npad * KP) return;
    int n = idx / KP, k = idx % KP;
    float v = 0.f;
    if (n < N_ && k < K_) {
        v = W[(size_t)k * N_ + n];
        if (useScale) v *= g_scale[k];
    }
    __nv_bfloat16 hv = __float2bfloat16(v);
    g_hB[idx] = hv;
    g_lB[idx] = __float2bfloat16(v - __bfloat162float(hv));
}

__global__ void k_zero_stats() {
    int i = threadIdx.x;
    g_sums[i] = 0.f;
    g_sumsq[i] = 0.f;
}
__global__ void k_finalize(const float* __restrict__ gg, const float* __restrict__ bb, int d) {
    int j = threadIdx.x;
    if (j < d) {
        float m   = g_sums[j] * (1.f / NN);
        float var = g_sumsq[j] * (1.f / NN) - m * m;
        float rs  = rsqrtf(var + EPSV);
        float sc  = rs * gg[j];
        g_scale[j] = sc;
        g_shift[j] = bb[j] - m * sc;
    }
}
__global__ void k_cvec(const float* __restrict__ W, int K_, int N_) {
    int n = threadIdx.x;
    if (n < N_) {
        float s = 0.f;
        for (int k = 0; k < K_; k++) s += g_shift[k] * W[(size_t)k * N_ + n];
        g_cvec[n] = s;
    } else {
        g_cvec[n] = 0.f;
    }
}

// ================= HMMA bf16 3-term split GEMM (templated N tile) ========
__device__ __forceinline__ void ldsm4(uint32_t& r0, uint32_t& r1, uint32_t& r2, uint32_t& r3,
                                      uint32_t addr) {
    asm volatile("ldmatrix.sync.aligned.m8n8.x4.shared.b16 {%0,%1,%2,%3}, [%4];"
        : "=r"(r0), "=r"(r1), "=r"(r2), "=r"(r3) : "r"(addr));
}
__device__ __forceinline__ void mma16816(float* d, uint32_t a0, uint32_t a1, uint32_t a2,
                                         uint32_t a3, uint32_t b0, uint32_t b1) {
    asm volatile(
        "mma.sync.aligned.m16n8k16.row.col.f32.bf16.bf16.f32 "
        "{%0,%1,%2,%3}, {%4,%5,%6,%7}, {%8,%9}, {%0,%1,%2,%3};"
        : "+f"(d[0]), "+f"(d[1]), "+f"(d[2]), "+f"(d[3])
        : "r"(a0), "r"(a1), "r"(a2), "r"(a3), "r"(b0), "r"(b1));
}
#define SWZ(r, q) (((uint32_t)(r) << 7) + ((((uint32_t)(q)) ^ ((uint32_t)(r) & 7)) << 4))

template <int JM8>
__global__ void __launch_bounds__(256, 2) k_hgemm(int KP, int strideOut, int useCvec,
                                                  int colOff, int outHalf) {
    constexpr int TMAX  = JM8 / 2;
    constexpr int BROWS = JM8 * 8;
    __shared__ __nv_bfloat16 sAh[128 * 64];
    __shared__ __nv_bfloat16 sAl[128 * 64];
    __shared__ __nv_bfloat16 sBh[64 * 64];
    __shared__ __nv_bfloat16 sBl[64 * 64];

    int tid = threadIdx.x;
    int warp = tid >> 5, lane = tid & 31;
    int rowbase = blockIdx.y * 128;
    int colbase = colOff + blockIdx.x * 64;

    float acc[JM8][4];
    #pragma unroll
    for (int j = 0; j < JM8; j++)
        #pragma unroll
        for (int q = 0; q < 4; q++) acc[j][q] = 0.f;

    uint32_t sAhB = smem_u32(sAh), sAlB = smem_u32(sAl);
    uint32_t sBhB = smem_u32(sBh), sBlB = smem_u32(sBl);

    int arow = warp * 16 + (lane & 15);
    int achk = lane >> 4;
    int brow = (lane & 7) + ((lane >> 4) << 3);
    int bchk = (lane >> 3) & 1;

    int nchunks = KP >> 6;
    for (int c = 0; c < nchunks; c++) {
        int k0 = c << 6;
        #pragma unroll
        for (int it = 0; it < 4; it++) {
            int u = tid + it * 256;
            int r = u >> 3, q = u & 7;
            int gr = rowbase + r;
            uint4 vh = make_uint4(0u, 0u, 0u, 0u);
            uint4 vl = vh;
            if (gr < NN) {
                size_t off = (size_t)gr * KP + k0 + q * 8;
                vh = *(const uint4*)(g_actH + off);
                vl = *(const uint4*)(g_actL + off);
            }
            uint32_t dz = SWZ(r, q);
            *(uint4*)((char*)sAh + dz) = vh;
            *(uint4*)((char*)sAl + dz) = vl;
        }
        #pragma unroll
        for (int it = 0; it < BROWS / 32; it++) {
            int u = tid + it * 256;
            int n = u >> 3, q = u & 7;
            size_t off = (size_t)(colbase + n) * KP + k0 + q * 8;
            uint32_t dz = SWZ(n, q);
            *(uint4*)((char*)sBh + dz) = *(const uint4*)(g_hB + off);
            *(uint4*)((char*)sBl + dz) = *(const uint4*)(g_lB + off);
        }
        __syncthreads();

        #pragma unroll
        for (int s = 0; s < 4; s++) {
            int aq = s * 2 + achk;
            uint32_t aoff = SWZ(arow, aq);
            uint32_t ah0, ah1, ah2, ah3, al0, al1, al2, al3;
            ldsm4(ah0, ah1, ah2, ah3, sAhB + aoff);
            ldsm4(al0, al1, al2, al3, sAlB + aoff);
            int bq = s * 2 + bchk;
            uint32_t bh[JM8 * 2], bl[JM8 * 2];
            #pragma unroll
            for (int t = 0; t < TMAX; t++) {
                uint32_t boff = SWZ(brow + t * 16, bq);
                ldsm4(bh[t*4], bh[t*4+1], bh[t*4+2], bh[t*4+3], sBhB + boff);
                ldsm4(bl[t*4], bl[t*4+1], bl[t*4+2], bl[t*4+3], sBlB + boff);
            }
            #pragma unroll
            for (int j = 0; j < JM8; j++) {
                mma16816(acc[j], ah0, ah1, ah2, ah3, bh[j*2], bh[j*2+1]);
                mma16816(acc[j], ah0, ah1, ah2, ah3, bl[j*2], bl[j*2+1]);
                mma16816(acc[j], al0, al1, al2, al3, bh[j*2], bh[j*2+1]);
            }
        }
        __syncthreads();
    }

    // epilogue: +cvec, store fp16 (layers 1-5) or fp32 (layer 6), tight stride
    int r0 = rowbase + warp * 16 + (lane >> 2);
    int c00 = colbase + (lane & 3) * 2;
    #pragma unroll
    for (int j = 0; j < JM8; j++) {
        int col = c00 + j * 8;
        if (col >= strideOut) continue;   // even stride, even col -> col+1 < strideOut too
        float cv0 = useCvec ? g_cvec[col] : 0.f;
        float cv1 = useCvec ? g_cvec[col + 1] : 0.f;
        float v00 = acc[j][0] + cv0, v01 = acc[j][1] + cv1;
        float v10 = acc[j][2] + cv0, v11 = acc[j][3] + cv1;
        if (outHalf) {
            if (r0 < NN)
                *(__half2*)(g_bufH + (size_t)r0 * strideOut + col) = __floats2half2_rn(v00, v01);
            if (r0 + 8 < NN)
                *(__half2*)(g_bufH + (size_t)(r0 + 8) * strideOut + col) = __floats2half2_rn(v10, v11);
        } else {
            if (r0 < NN) {
                float* p = g_bufA + (size_t)r0 * strideOut + col;
                p[0] = v00; p[1] = v01;
            }
            if (r0 + 8 < NN) {
                float* p = g_bufA + (size_t)(r0 + 8) * strideOut + col;
                p[0] = v10; p[1] = v11;
            }
        }
    }
}

// ===== aggregation over fp16 h (layers 1-5): +bias, relu, bf16 split-out, fused BN stats =====
// 8 halves (one float4) per lane-group element; s8 = strideH/8 groups per row.
template <int EPG>
__global__ void __launch_bounds__(256) k_aggH(const float* __restrict__ bias,
                                              int d, int s8, int KPn)
{
    constexpr int G = 32 / EPG;
    int lane = threadIdx.x & 31;
    int warp = threadIdx.x >> 5;
    int sub  = lane & (G - 1);
    int grp  = lane / G;

    __shared__ float sh_sum[256], sh_sq[256];
    if (threadIdx.x < 256) { sh_sum[threadIdx.x] = 0.f; sh_sq[threadIdx.x] = 0.f; }
    __syncthreads();

    float st_s[8], st_q[8];
    #pragma unroll
    for (int i = 0; i < 8; i++) { st_s[i] = 0.f; st_q[i] = 0.f; }

    const float4* __restrict__ H8 = (const float4*)g_bufH;
    const __nv_bfloat16 bz = __float2bfloat16(0.f);
    bool lactive;
    {
        lactive = (sub < s8);
    }

    for (int node = blockIdx.x * 8 + warp; node < NN; node += gridDim.x * 8) {
        float acc8[8];
        #pragma unroll
        for (int i = 0; i < 8; i++) acc8[i] = 0.f;

        float dn = g_dis[node];
        if (grp == 0 && lactive) {
            float sw = dn * dn;
            float4 v = H8[(size_t)node * s8 + sub];
            const __half2* h2 = reinterpret_cast<const __half2*>(&v);
            #pragma unroll
            for (int i = 0; i < 4; i++) {
                float2 t = __half22float2(h2[i]);
                acc8[2*i]   = sw * t.x;
                acc8[2*i+1] = sw * t.y;
            }
        }

        int start = g_rowptr[node], end = g_rowptr[node + 1];
        for (int base = start; base < end; base += 32) {
            int e = base + lane;
            int ssrc = 0; float ww = 0.f;
            if (e < end) { ssrc = g_src[e]; ww = g_w[e]; }
            int cnt = min(32, end - base);
            int steps = (cnt + EPG - 1) / EPG;
            for (int t = 0; t < steps; t++) {
                int ei = t * EPG + grp;
                int   s2 = __shfl_sync(0xffffffffu, ssrc, ei);
                float w2 = __shfl_sync(0xffffffffu, ww, ei);
                if (ei < cnt && lactive) {
                    float4 v = H8[(size_t)s2 * s8 + sub];
                    const __half2* h2 = reinterpret_cast<const __half2*>(&v);
                    #pragma unroll
                    for (int i = 0; i < 4; i++) {
                        float2 tt = __half22float2(h2[i]);
                        acc8[2*i]   += w2 * tt.x;
                        acc8[2*i+1] += w2 * tt.y;
                    }
                }
            }
        }

        if (EPG > 1) {
            #pragma unroll
            for (int off = G; off < 32; off <<= 1) {
                #pragma unroll
                for (int i = 0; i < 8; i++)
                    acc8[i] += __shfl_xor_sync(0xffffffffu, acc8[i], off);
            }
        }

        if (grp == 0) {
            if (lactive) {
                #pragma unroll
                for (int i = 0; i < 8; i++) {
                    int col = sub * 8 + i;
                    if (col < d) {
                        float v = fmaxf(acc8[i] + bias[col], 0.f);
                        __nv_bfloat16 hv = __float2bfloat16(v);
                        g_actH[(size_t)node * KPn + col] = hv;
                        g_actL[(size_t)node * KPn + col] =
                            __float2bfloat16(v - __bfloat162float(hv));
                        st_s[i] += v;
                        st_q[i] += v * v;
                    }
                }
            }
            for (int col = d + sub; col < KPn; col += G) {
                g_actH[(size_t)node * KPn + col] = bz;
                g_actL[(size_t)node * KPn + col] = bz;
            }
        }
    }

    __syncthreads();
    if (grp == 0 && lactive) {
        #pragma unroll
        for (int i = 0; i < 8; i++) {
            int col = sub * 8 + i;
            if (col < d) {
                atomicAdd(&sh_sum[col], st_s[i]);
                atomicAdd(&sh_sq[col],  st_q[i]);
            }
        }
    }
    __syncthreads();
    if (threadIdx.x < d) {
        atomicAdd(&g_sums[threadIdx.x],  sh_sum[threadIdx.x]);
        atomicAdd(&g_sumsq[threadIdx.x], sh_sq[threadIdx.x]);
    }
}

// ===== final aggregation (layer 6): fp32 gather, +bias, log_softmax =====
__global__ void __launch_bounds__(256) k_aggLast(const float* __restrict__ bias,
                                                 float* __restrict__ outp, int d, int s4)
{
    constexpr int EPG = 4, G = 8;
    int lane = threadIdx.x & 31;
    int warp = threadIdx.x >> 5;
    int sub  = lane & (G - 1);
    int grp  = lane / G;

    const float4* __restrict__ H = (const float4*)g_bufA;

    for (int node = blockIdx.x * 8 + warp; node < NN; node += gridDim.x * 8) {
        float4 acc = make_float4(0.f, 0.f, 0.f, 0.f);
        float dn = g_dis[node];
        if (grp == 0 && sub < s4) {
            float sw = dn * dn;
            float4 h = H[(size_t)node * s4 + sub];
            acc.x = sw * h.x; acc.y = sw * h.y; acc.z = sw * h.z; acc.w = sw * h.w;
        }

        int start = g_rowptr[node], end = g_rowptr[node + 1];
        for (int base = start; base < end; base += 32) {
            int e = base + lane;
            int ssrc = 0; float ww = 0.f;
            if (e < end) { ssrc = g_src[e]; ww = g_w[e]; }
            int cnt = min(32, end - base);
            int steps = (cnt + EPG - 1) / EPG;
            for (int t = 0; t < steps; t++) {
                int ei = t * EPG + grp;
                int   s2 = __shfl_sync(0xffffffffu, ssrc, ei);
                float w2 = __shfl_sync(0xffffffffu, ww, ei);
                if (ei < cnt && sub < s4) {
                    float4 h = H[(size_t)s2 * s4 + sub];
                    acc.x += w2 * h.x; acc.y += w2 * h.y;
                    acc.z += w2 * h.z; acc.w += w2 * h.w;
                }
            }
        }

        #pragma unroll
        for (int off = G; off < 32; off <<= 1) {
            acc.x += __shfl_xor_sync(0xffffffffu, acc.x, off);
            acc.y += __shfl_xor_sync(0xffffffffu, acc.y, off);
            acc.z += __shfl_xor_sync(0xffffffffu, acc.z, off);
            acc.w += __shfl_xor_sync(0xffffffffu, acc.w, off);
        }

        // log_softmax across warp (grp 0 holds sums)
        float vals[4] = {acc.x, acc.y, acc.z, acc.w};
        float lmax = -INFINITY;
        #pragma unroll
        for (int q = 0; q < 4; q++) {
            int col = sub * 4 + q;
            float v = (grp == 0 && col < d) ? vals[q] + bias[col] : -INFINITY;
            vals[q] = v;
            lmax = fmaxf(lmax, v);
        }
        #pragma unroll
        for (int off = 1; off < G; off <<= 1)
            lmax = fmaxf(lmax, __shfl_xor_sync(0xffffffffu, lmax, off));
        float lsum = 0.f;
        #pragma unroll
        for (int q = 0; q < 4; q++) {
            int col = sub * 4 + q;
            if (grp == 0 && col < d) lsum += expf(vals[q] - lmax);
        }
        #pragma unroll
        for (int off = 1; off < G; off <<= 1)
            lsum += __shfl_xor_sync(0xffffffffu, lsum, off);
        float lse = logf(lsum) + lmax;
        if (grp == 0) {
            #pragma unroll
            for (int q = 0; q < 4; q++) {
                int col = sub * 4 + q;
                if (col < d) outp[(size_t)node * d + col] = vals[q] - lse;
            }
        }
    }
}

// ================= launch =================
extern "C" void kernel_launch(void* const* d_in, const int* in_sizes, int n_in,
                              void* d_out, int out_size) {
    const float* x  = (const float*)d_in[0];
    const int*   ei = (const int*)d_in[1];
    static const int DIMS_[7]  = {220, 220, 150, 100, 60, 30, 17};
    static const int KPt[6]    = {256, 256, 192, 128, 64, 64};    // GEMM K stride
    static const int NPADc[6]  = {224, 160, 128, 64, 32, 32};     // GEMM compute cols (B rows)
    static const int STRIDEo[6]= {224, 152, 104, 64, 32, 20};     // h store stride (tight)
    const float* W[6]; const float* b[6];
    for (int i = 0; i < 6; i++) {
        W[i] = (const float*)d_in[2 + 2 * i];
        b[i] = (const float*)d_in[3 + 2 * i];
    }
    const float* gpar[5]; const float* bpar[5];
    for (int i = 0; i < 5; i++) {
        gpar[i] = (const float*)d_in[14 + 2 * i];
        bpar[i] = (const float*)d_in[15 + 2 * i];
    }

    // preprocessing
    k_init<<<(NN + 255) / 256, 256>>>();
    k_hist<<<(EE + 255) / 256, 256>>>(ei + EE);
    k_dis<<<(NN + 255) / 256, 256>>>();
    int nb = (NN + 511) / 512;
    k_scan1<<<nb, 512>>>();
    k_scan2<<<1, 256>>>(nb);
    k_scan3<<<nb, 512>>>();
    k_fill<<<(EE + 255) / 256, 256>>>(ei);
    k_convX<<<NN, 256>>>(x);

    const int AGG_GRID = 1184;
    const int ROW_BLKS = (NN + 127) / 128;   // 782

    for (int L = 0; L < 6; L++) {
        int K_ = DIMS_[L], Nc = DIMS_[L + 1];
        int KP = KPt[L], Npad = NPADc[L], so = STRIDEo[L];
        int outHalf = (L < 5) ? 1 : 0;

        if (L > 0) {
            k_finalize<<<1, 256>>>(gpar[L - 1], bpar[L - 1], K_);
            k_cvec<<<1, 256>>>(W[L], K_, Nc);
        }
        k_prepW<<<(Npad * KP + 255) / 256, 256>>>(W[L], K_, Nc, KP, Npad, L > 0 ? 1 : 0);

        int nfull = Npad / 64;
        int tail  = Npad - nfull * 64;
        int uc = L > 0 ? 1 : 0;
        if (nfull > 0) {
            dim3 gg(nfull, ROW_BLKS);
            k_hgemm<8><<<gg, 256>>>(KP, so, uc, 0, outHalf);
        }
        if (tail > 0) {
            dim3 gg(1, ROW_BLKS);
            k_hgemm<4><<<gg, 256>>>(KP, so, uc, nfull * 64, outHalf);
        }

        if (L < 5) {
            k_zero_stats<<<1, 256>>>();
            int s8 = so / 8;                 // 28, 19, 13, 8, 4
            int KPn = KPt[L + 1];
            if (L <= 1)      k_aggH<1><<<AGG_GRID, 256>>>(b[L], Nc, s8, KPn);
            else if (L == 2) k_aggH<2><<<AGG_GRID, 256>>>(b[L], Nc, s8, KPn);
            else if (L == 3) k_aggH<4><<<AGG_GRID, 256>>>(b[L], Nc, s8, KPn);
            else             k_aggH<8><<<AGG_GRID, 256>>>(b[L], Nc, s8, KPn);
        } else {
            k_aggLast<<<AGG_GRID, 256>>>(b[L], (float*)d_out, Nc, so / 4);
        }
    }
}

// round 9
// speedup vs baseline: 1.9955x; 1.0914x over previous
#include <cuda_runtime.h>
#include <cuda_bf16.h>
#include <cuda_fp16.h>
#include <math.h>
#include <stdint.h>

#define NN 100000
#define EE 1600000
#define EPSV 1e-5f

// ================= device scratch =================
__device__ __nv_bfloat16 g_actH[(size_t)NN * 256];   // activation bf16 hi, row stride KP
__device__ __nv_bfloat16 g_actL[(size_t)NN * 256];   // activation bf16 lo
__device__ __half g_bufH[(size_t)NN * 224];          // GEMM output fp16 (layers 1-5), tight stride
__device__ float  g_bufA[(size_t)NN * 20];           // GEMM output fp32 (layer 6), stride 20
__device__ __nv_bfloat16 g_hB[57344];                // W^T bf16 hi, [Npad, KP]
__device__ __nv_bfloat16 g_lB[57344];                // W^T bf16 lo
__device__ int   g_deg[NN];
__device__ float g_dis[NN];
__device__ int   g_cnt[NN];
__device__ int   g_rowptr[NN + 1];
__device__ int   g_cursor[NN];
__device__ int   g_blocksum[256];
__device__ int   g_blockoff[256];
__device__ int   g_src[EE];
__device__ float g_w[EE];
__device__ float g_sumsA[5][256];    // per-layer BN stats (double-buffered by layer)
__device__ float g_sumsqA[5][256];
__device__ float g_cvec[256];

__device__ __forceinline__ uint32_t smem_u32(const void* p) {
    uint32_t a;
    asm("{ .reg .u64 t; cvta.to.shared.u64 t, %1; cvt.u32.u64 %0, t; }" : "=r"(a) : "l"(p));
    return a;
}

// ================= preprocessing =================
__global__ void k_zero() {
    int i = blockIdx.x * blockDim.x + threadIdx.x;
    if (i < NN) g_deg[i] = 0;
    if (i < 5 * 256) {
        ((float*)g_sumsA)[i]  = 0.f;
        ((float*)g_sumsqA)[i] = 0.f;
    }
}
__global__ void k_hist(const int* __restrict__ dst) {
    int e = blockIdx.x * blockDim.x + threadIdx.x;
    if (e < EE) atomicAdd(&g_deg[dst[e]], 1);
}
__global__ void k_dis() {
    int i = blockIdx.x * blockDim.x + threadIdx.x;
    if (i < NN) {
        int in = g_deg[i];
        g_dis[i] = rsqrtf((float)(in + 1));   // self loop included
        g_cnt[i] = in;
    }
}
__global__ void k_scan1() {
    __shared__ int sh[512];
    int i = blockIdx.x * 512 + threadIdx.x;
    int v = (i < NN) ? g_cnt[i] : 0;
    sh[threadIdx.x] = v;
    __syncthreads();
    #pragma unroll
    for (int off = 1; off < 512; off <<= 1) {
        int t = (threadIdx.x >= off) ? sh[threadIdx.x - off] : 0;
        __syncthreads();
        sh[threadIdx.x] += t;
        __syncthreads();
    }
    if (i < NN) g_rowptr[i] = sh[threadIdx.x] - v;
    if (threadIdx.x == 511) g_blocksum[blockIdx.x] = sh[511];
}
__global__ void k_scan2(int nb) {
    __shared__ int sh[256];
    int v = (threadIdx.x < nb) ? g_blocksum[threadIdx.x] : 0;
    sh[threadIdx.x] = v;
    __syncthreads();
    #pragma unroll
    for (int off = 1; off < 256; off <<= 1) {
        int t = (threadIdx.x >= off) ? sh[threadIdx.x - off] : 0;
        __syncthreads();
        sh[threadIdx.x] += t;
        __syncthreads();
    }
    if (threadIdx.x < nb) g_blockoff[threadIdx.x] = sh[threadIdx.x] - v;
}
__global__ void k_scan3() {
    int i = blockIdx.x * 512 + threadIdx.x;
    if (i < NN) {
        int r = g_rowptr[i] + g_blockoff[blockIdx.x];
        g_rowptr[i] = r;
        g_cursor[i] = r;
    }
    if (i == 0 && blockIdx.x == 0) g_rowptr[NN] = EE;
}
__global__ void k_fill(const int* __restrict__ ei) {
    int e = blockIdx.x * blockDim.x + threadIdx.x;
    if (e < EE) {
        int s  = ei[e];
        int dv = ei[EE + e];
        float w = g_dis[s] * g_dis[dv];
        int p = atomicAdd(&g_cursor[dv], 1);
        g_src[p] = s;
        g_w[p]   = w;
    }
}

// ================= conversions / merged per-layer prep =================
__global__ void k_convX(const float* __restrict__ x) {
    int i = blockIdx.x;
    int k = threadIdx.x;
    float v = (k < 220) ? x[(size_t)i * 220 + k] : 0.f;
    __nv_bfloat16 hv = __float2bfloat16(v);
    g_actH[(size_t)i * 256 + k] = hv;
    g_actL[(size_t)i * 256 + k] = __float2bfloat16(v - __bfloat162float(hv));
}

// One block per output row n (Npad blocks): computes BN scale/shift from stats,
// writes scaled W^T row (bf16 hi/lo), and cvec[n] = shift @ W[:,n].
__global__ void __launch_bounds__(256) k_prepLayer(
    const float* __restrict__ W, const float* __restrict__ gg, const float* __restrict__ bb,
    int K_, int N_, int KP, int useScale, int statIdx)
{
    __shared__ float s_scale[256], s_shift[256], s_red[256];
    int t = threadIdx.x;
    int n = blockIdx.x;

    float sc = 1.f, sh = 0.f;
    if (useScale && t < K_) {
        float m   = g_sumsA[statIdx][t] * (1.f / NN);
        float var = g_sumsqA[statIdx][t] * (1.f / NN) - m * m;
        float rs  = rsqrtf(var + EPSV);
        sc = rs * gg[t];
        sh = bb[t] - m * sc;
    }
    s_scale[t] = sc;
    s_shift[t] = sh;
    __syncthreads();

    // scaled W^T row (zero-padded)
    for (int k = t; k < KP; k += 256) {
        float v = 0.f;
        if (n < N_ && k < K_) v = W[(size_t)k * N_ + n] * s_scale[k];
        __nv_bfloat16 hv = __float2bfloat16(v);
        g_hB[(size_t)n * KP + k] = hv;
        g_lB[(size_t)n * KP + k] = __float2bfloat16(v - __bfloat162float(hv));
    }

    // cvec[n] = sum_k shift[k] * W[k][n]
    if (useScale) {
        float part = 0.f;
        if (n < N_)
            for (int k = t; k < K_; k += 256) part += s_shift[k] * W[(size_t)k * N_ + n];
        s_red[t] = part;
        __syncthreads();
        #pragma unroll
        for (int off = 128; off > 0; off >>= 1) {
            if (t < off) s_red[t] += s_red[t + off];
            __syncthreads();
        }
        if (t == 0) g_cvec[n] = s_red[0];
    }
}

// ================= HMMA bf16 3-term split GEMM (templated N tile) ========
__device__ __forceinline__ void ldsm4(uint32_t& r0, uint32_t& r1, uint32_t& r2, uint32_t& r3,
                                      uint32_t addr) {
    asm volatile("ldmatrix.sync.aligned.m8n8.x4.shared.b16 {%0,%1,%2,%3}, [%4];"
        : "=r"(r0), "=r"(r1), "=r"(r2), "=r"(r3) : "r"(addr));
}
__device__ __forceinline__ void mma16816(float* d, uint32_t a0, uint32_t a1, uint32_t a2,
                                         uint32_t a3, uint32_t b0, uint32_t b1) {
    asm volatile(
        "mma.sync.aligned.m16n8k16.row.col.f32.bf16.bf16.f32 "
        "{%0,%1,%2,%3}, {%4,%5,%6,%7}, {%8,%9}, {%0,%1,%2,%3};"
        : "+f"(d[0]), "+f"(d[1]), "+f"(d[2]), "+f"(d[3])
        : "r"(a0), "r"(a1), "r"(a2), "r"(a3), "r"(b0), "r"(b1));
}
#define SWZ(r, q) (((uint32_t)(r) << 7) + ((((uint32_t)(q)) ^ ((uint32_t)(r) & 7)) << 4))

template <int JM8>
__global__ void __launch_bounds__(256, 2) k_hgemm(int KP, int strideOut, int useCvec,
                                                  int colOff, int outHalf) {
    constexpr int TMAX  = JM8 / 2;
    constexpr int BROWS = JM8 * 8;
    __shared__ __nv_bfloat16 sAh[128 * 64];
    __shared__ __nv_bfloat16 sAl[128 * 64];
    __shared__ __nv_bfloat16 sBh[64 * 64];
    __shared__ __nv_bfloat16 sBl[64 * 64];

    int tid = threadIdx.x;
    int warp = tid >> 5, lane = tid & 31;
    int rowbase = blockIdx.y * 128;
    int colbase = colOff + blockIdx.x * 64;

    float acc[JM8][4];
    #pragma unroll
    for (int j = 0; j < JM8; j++)
        #pragma unroll
        for (int q = 0; q < 4; q++) acc[j][q] = 0.f;

    uint32_t sAhB = smem_u32(sAh), sAlB = smem_u32(sAl);
    uint32_t sBhB = smem_u32(sBh), sBlB = smem_u32(sBl);

    int arow = warp * 16 + (lane & 15);
    int achk = lane >> 4;
    int brow = (lane & 7) + ((lane >> 4) << 3);
    int bchk = (lane >> 3) & 1;

    int nchunks = KP >> 6;
    for (int c = 0; c < nchunks; c++) {
        int k0 = c << 6;
        #pragma unroll
        for (int it = 0; it < 4; it++) {
            int u = tid + it * 256;
            int r = u >> 3, q = u & 7;
            int gr = rowbase + r;
            uint4 vh = make_uint4(0u, 0u, 0u, 0u);
            uint4 vl = vh;
            if (gr < NN) {
                size_t off = (size_t)gr * KP + k0 + q * 8;
                vh = *(const uint4*)(g_actH + off);
                vl = *(const uint4*)(g_actL + off);
            }
            uint32_t dz = SWZ(r, q);
            *(uint4*)((char*)sAh + dz) = vh;
            *(uint4*)((char*)sAl + dz) = vl;
        }
        #pragma unroll
        for (int it = 0; it < BROWS / 32; it++) {
            int u = tid + it * 256;
            int n = u >> 3, q = u & 7;
            size_t off = (size_t)(colbase + n) * KP + k0 + q * 8;
            uint32_t dz = SWZ(n, q);
            *(uint4*)((char*)sBh + dz) = *(const uint4*)(g_hB + off);
            *(uint4*)((char*)sBl + dz) = *(const uint4*)(g_lB + off);
        }
        __syncthreads();

        #pragma unroll
        for (int s = 0; s < 4; s++) {
            int aq = s * 2 + achk;
            uint32_t aoff = SWZ(arow, aq);
            uint32_t ah0, ah1, ah2, ah3, al0, al1, al2, al3;
            ldsm4(ah0, ah1, ah2, ah3, sAhB + aoff);
            ldsm4(al0, al1, al2, al3, sAlB + aoff);
            int bq = s * 2 + bchk;
            uint32_t bh[JM8 * 2], bl[JM8 * 2];
            #pragma unroll
            for (int t = 0; t < TMAX; t++) {
                uint32_t boff = SWZ(brow + t * 16, bq);
                ldsm4(bh[t*4], bh[t*4+1], bh[t*4+2], bh[t*4+3], sBhB + boff);
                ldsm4(bl[t*4], bl[t*4+1], bl[t*4+2], bl[t*4+3], sBlB + boff);
            }
            #pragma unroll
            for (int j = 0; j < JM8; j++) {
                mma16816(acc[j], ah0, ah1, ah2, ah3, bh[j*2], bh[j*2+1]);
                mma16816(acc[j], ah0, ah1, ah2, ah3, bl[j*2], bl[j*2+1]);
                mma16816(acc[j], al0, al1, al2, al3, bh[j*2], bh[j*2+1]);
            }
        }
        __syncthreads();
    }

    int r0 = rowbase + warp * 16 + (lane >> 2);
    int c00 = colbase + (lane & 3) * 2;
    #pragma unroll
    for (int j = 0; j < JM8; j++) {
        int col = c00 + j * 8;
        if (col >= strideOut) continue;
        float cv0 = useCvec ? g_cvec[col] : 0.f;
        float cv1 = useCvec ? g_cvec[col + 1] : 0.f;
        float v00 = acc[j][0] + cv0, v01 = acc[j][1] + cv1;
        float v10 = acc[j][2] + cv0, v11 = acc[j][3] + cv1;
        if (outHalf) {
            if (r0 < NN)
                *(__half2*)(g_bufH + (size_t)r0 * strideOut + col) = __floats2half2_rn(v00, v01);
            if (r0 + 8 < NN)
                *(__half2*)(g_bufH + (size_t)(r0 + 8) * strideOut + col) = __floats2half2_rn(v10, v11);
        } else {
            if (r0 < NN) {
                float* p = g_bufA + (size_t)r0 * strideOut + col;
                p[0] = v00; p[1] = v01;
            }
            if (r0 + 8 < NN) {
                float* p = g_bufA + (size_t)(r0 + 8) * strideOut + col;
                p[0] = v10; p[1] = v11;
            }
        }
    }
}

// ===== aggregation over fp16 h (layers 1-5): +bias, relu, vectorized bf16 split-out, BN stats ===
template <int EPG>
__global__ void __launch_bounds__(256) k_aggH(const float* __restrict__ bias,
                                              int d, int s8, int KPn, int statIdx)
{
    constexpr int G = 32 / EPG;
    int lane = threadIdx.x & 31;
    int warp = threadIdx.x >> 5;
    int sub  = lane & (G - 1);
    int grp  = lane / G;

    __shared__ float sh_sum[256], sh_sq[256], sh_bias[256];
    if (threadIdx.x < 256) {
        sh_sum[threadIdx.x] = 0.f;
        sh_sq[threadIdx.x] = 0.f;
        sh_bias[threadIdx.x] = (threadIdx.x < d) ? bias[threadIdx.x] : 0.f;
    }
    __syncthreads();

    float st_s[8], st_q[8];
    #pragma unroll
    for (int i = 0; i < 8; i++) { st_s[i] = 0.f; st_q[i] = 0.f; }

    const float4* __restrict__ H8 = (const float4*)g_bufH;
    bool lactive = (sub < s8);
    int nsg = KPn >> 3;

    for (int node = blockIdx.x * 8 + warp; node < NN; node += gridDim.x * 8) {
        float acc8[8];
        #pragma unroll
        for (int i = 0; i < 8; i++) acc8[i] = 0.f;

        float dn = g_dis[node];
        if (grp == 0 && lactive) {
            float sw = dn * dn;
            float4 v = H8[(size_t)node * s8 + sub];
            const __half2* h2 = reinterpret_cast<const __half2*>(&v);
            #pragma unroll
            for (int i = 0; i < 4; i++) {
                float2 t = __half22float2(h2[i]);
                acc8[2*i]   = sw * t.x;
                acc8[2*i+1] = sw * t.y;
            }
        }

        int start = g_rowptr[node], end = g_rowptr[node + 1];
        for (int base = start; base < end; base += 32) {
            int e = base + lane;
            int ssrc = 0; float ww = 0.f;
            if (e < end) { ssrc = g_src[e]; ww = g_w[e]; }
            int cnt = min(32, end - base);
            int steps = (cnt + EPG - 1) / EPG;
            for (int t = 0; t < steps; t++) {
                int ei = t * EPG + grp;
                int   s2 = __shfl_sync(0xffffffffu, ssrc, ei);
                float w2 = __shfl_sync(0xffffffffu, ww, ei);
                if (ei < cnt && lactive) {
                    float4 v = H8[(size_t)s2 * s8 + sub];
                    const __half2* h2 = reinterpret_cast<const __half2*>(&v);
                    #pragma unroll
                    for (int i = 0; i < 4; i++) {
                        float2 tt = __half22float2(h2[i]);
                        acc8[2*i]   += w2 * tt.x;
                        acc8[2*i+1] += w2 * tt.y;
                    }
                }
            }
        }

        if (EPG > 1) {
            #pragma unroll
            for (int off = G; off < 32; off <<= 1) {
                #pragma unroll
                for (int i = 0; i < 8; i++)
                    acc8[i] += __shfl_xor_sync(0xffffffffu, acc8[i], off);
            }
        }

        // vectorized epilogue: each store-group g covers cols [8g, 8g+8)
        if (grp == 0) {
            for (int g = sub; g < nsg; g += G) {
                bool own = (g == sub);
                uint4 ph, pl;
                __nv_bfloat16* hp = (__nv_bfloat16*)&ph;
                __nv_bfloat16* lp = (__nv_bfloat16*)&pl;
                #pragma unroll
                for (int i = 0; i < 8; i++) {
                    int col = g * 8 + i;
                    float v = 0.f;
                    if (own && col < d) {
                        v = fmaxf(acc8[i] + sh_bias[col], 0.f);
                        st_s[i] += v;
                        st_q[i] += v * v;
                    }
                    __nv_bfloat16 hv = __float2bfloat16(v);
                    hp[i] = hv;
                    lp[i] = __float2bfloat16(v - __bfloat162float(hv));
                }
                *(uint4*)(g_actH + (size_t)node * KPn + g * 8) = ph;
                *(uint4*)(g_actL + (size_t)node * KPn + g * 8) = pl;
            }
        }
    }

    __syncthreads();
    if (grp == 0 && lactive) {
        #pragma unroll
        for (int i = 0; i < 8; i++) {
            int col = sub * 8 + i;
            if (col < d) {
                atomicAdd(&sh_sum[col], st_s[i]);
                atomicAdd(&sh_sq[col],  st_q[i]);
            }
        }
    }
    __syncthreads();
    if (threadIdx.x < d) {
        atomicAdd(&g_sumsA[statIdx][threadIdx.x],  sh_sum[threadIdx.x]);
        atomicAdd(&g_sumsqA[statIdx][threadIdx.x], sh_sq[threadIdx.x]);
    }
}

// ===== final aggregation (layer 6): fp32 gather, +bias, log_softmax =====
__global__ void __launch_bounds__(256) k_aggLast(const float* __restrict__ bias,
                                                 float* __restrict__ outp, int d, int s4)
{
    constexpr int EPG = 4, G = 8;
    int lane = threadIdx.x & 31;
    int warp = threadIdx.x >> 5;
    int sub  = lane & (G - 1);
    int grp  = lane / G;

    const float4* __restrict__ H = (const float4*)g_bufA;

    for (int node = blockIdx.x * 8 + warp; node < NN; node += gridDim.x * 8) {
        float4 acc = make_float4(0.f, 0.f, 0.f, 0.f);
        float dn = g_dis[node];
        if (grp == 0 && sub < s4) {
            float sw = dn * dn;
            float4 h = H[(size_t)node * s4 + sub];
            acc.x = sw * h.x; acc.y = sw * h.y; acc.z = sw * h.z; acc.w = sw * h.w;
        }

        int start = g_rowptr[node], end = g_rowptr[node + 1];
        for (int base = start; base < end; base += 32) {
            int e = base + lane;
            int ssrc = 0; float ww = 0.f;
            if (e < end) { ssrc = g_src[e]; ww = g_w[e]; }
            int cnt = min(32, end - base);
            int steps = (cnt + EPG - 1) / EPG;
            for (int t = 0; t < steps; t++) {
                int ei = t * EPG + grp;
                int   s2 = __shfl_sync(0xffffffffu, ssrc, ei);
                float w2 = __shfl_sync(0xffffffffu, ww, ei);
                if (ei < cnt && sub < s4) {
                    float4 h = H[(size_t)s2 * s4 + sub];
                    acc.x += w2 * h.x; acc.y += w2 * h.y;
                    acc.z += w2 * h.z; acc.w += w2 * h.w;
                }
            }
        }

        #pragma unroll
        for (int off = G; off < 32; off <<= 1) {
            acc.x += __shfl_xor_sync(0xffffffffu, acc.x, off);
            acc.y += __shfl_xor_sync(0xffffffffu, acc.y, off);
            acc.z += __shfl_xor_sync(0xffffffffu, acc.z, off);
            acc.w += __shfl_xor_sync(0xffffffffu, acc.w, off);
        }

        float vals[4] = {acc.x, acc.y, acc.z, acc.w};
        float lmax = -INFINITY;
        #pragma unroll
        for (int q = 0; q < 4; q++) {
            int col = sub * 4 + q;
            float v = (grp == 0 && col < d) ? vals[q] + bias[col] : -INFINITY;
            vals[q] = v;
            lmax = fmaxf(lmax, v);
        }
        #pragma unroll
        for (int off = 1; off < G; off <<= 1)
            lmax = fmaxf(lmax, __shfl_xor_sync(0xffffffffu, lmax, off));
        float lsum = 0.f;
        #pragma unroll
        for (int q = 0; q < 4; q++) {
            int col = sub * 4 + q;
            if (grp == 0 && col < d) lsum += expf(vals[q] - lmax);
        }
        #pragma unroll
        for (int off = 1; off < G; off <<= 1)
            lsum += __shfl_xor_sync(0xffffffffu, lsum, off);
        float lse = logf(lsum) + lmax;
        if (grp == 0) {
            #pragma unroll
            for (int q = 0; q < 4; q++) {
                int col = sub * 4 + q;
                if (col < d) outp[(size_t)node * d + col] = vals[q] - lse;
            }
        }
    }
}

// ================= launch =================
extern "C" void kernel_launch(void* const* d_in, const int* in_sizes, int n_in,
                              void* d_out, int out_size) {
    const float* x  = (const float*)d_in[0];
    const int*   ei = (const int*)d_in[1];
    static const int DIMS_[7]  = {220, 220, 150, 100, 60, 30, 17};
    static const int KPt[6]    = {256, 256, 192, 128, 64, 64};
    static const int NPADc[6]  = {224, 160, 128, 64, 32, 32};
    static const int STRIDEo[6]= {224, 152, 104, 64, 32, 20};
    const float* W[6]; const float* b[6];
    for (int i = 0; i < 6; i++) {
        W[i] = (const float*)d_in[2 + 2 * i];
        b[i] = (const float*)d_in[3 + 2 * i];
    }
    const float* gpar[5]; const float* bpar[5];
    for (int i = 0; i < 5; i++) {
        gpar[i] = (const float*)d_in[14 + 2 * i];
        bpar[i] = (const float*)d_in[15 + 2 * i];
    }

    // preprocessing
    k_zero<<<(NN + 255) / 256, 256>>>();
    k_hist<<<(EE + 255) / 256, 256>>>(ei + EE);
    k_dis<<<(NN + 255) / 256, 256>>>();
    int nb = (NN + 511) / 512;
    k_scan1<<<nb, 512>>>();
    k_scan2<<<1, 256>>>(nb);
    k_scan3<<<nb, 512>>>();
    k_fill<<<(EE + 255) / 256, 256>>>(ei);
    k_convX<<<NN, 256>>>(x);

    const int AGG_GRID = 1184;
    const int ROW_BLKS = (NN + 127) / 128;

    for (int L = 0; L < 6; L++) {
        int K_ = DIMS_[L], Nc = DIMS_[L + 1];
        int KP = KPt[L], Npad = NPADc[L], so = STRIDEo[L];
        int outHalf = (L < 5) ? 1 : 0;
        int uc = L > 0 ? 1 : 0;

        k_prepLayer<<<Npad, 256>>>(W[L],
                                   L > 0 ? gpar[L - 1] : nullptr,
                                   L > 0 ? bpar[L - 1] : nullptr,
                                   K_, Nc, KP, uc, L > 0 ? L - 1 : 0);

        int nfull = Npad / 64;
        int tail  = Npad - nfull * 64;
        if (nfull > 0) {
            dim3 gg(nfull, ROW_BLKS);
            k_hgemm<8><<<gg, 256>>>(KP, so, uc, 0, outHalf);
        }
        if (tail > 0) {
            dim3 gg(1, ROW_BLKS);
            k_hgemm<4><<<gg, 256>>>(KP, so, uc, nfull * 64, outHalf);
        }

        if (L < 5) {
            int s8 = so / 8;
            int KPn = KPt[L + 1];
            if (L <= 1)      k_aggH<1><<<AGG_GRID, 256>>>(b[L], Nc, s8, KPn, L);
            else if (L == 2) k_aggH<2><<<AGG_GRID, 256>>>(b[L], Nc, s8, KPn, L);
            else if (L == 3) k_aggH<4><<<AGG_GRID, 256>>>(b[L], Nc, s8, KPn, L);
            else             k_aggH<8><<<AGG_GRID, 256>>>(b[L], Nc, s8, KPn, L);
        } else {
            k_aggLast<<<AGG_GRID, 256>>>(b[L], (float*)d_out, Nc, so / 4);
        }
    }
}

// round 10
// speedup vs baseline: 2.1555x; 1.0801x over previous
#include <cuda_runtime.h>
#include <cuda_bf16.h>
#include <cuda_fp16.h>
#include <math.h>
#include <stdint.h>

#define NN 100000
#define EE 1600000
#define EPSV 1e-5f

// ================= device scratch =================
__device__ __half g_actF[(size_t)NN * 256];          // activation fp16, row stride KP
__device__ __half g_bufH[(size_t)NN * 224];          // GEMM output fp16 (layers 1-5), tight stride
__device__ float  g_bufA[(size_t)NN * 20];           // GEMM output fp32 (layer 6), stride 20
__device__ __nv_bfloat16 g_hB[57344];                // W^T bf16 hi, [Npad, KP]
__device__ __nv_bfloat16 g_lB[57344];                // W^T bf16 lo
__device__ int   g_deg[NN];
__device__ float g_dis[NN];
__device__ int   g_cnt[NN];
__device__ int   g_rowptr[NN + 1];
__device__ int   g_cursor[NN];
__device__ int   g_blocksum[256];
__device__ int   g_blockoff[256];
__device__ int   g_src[EE];
__device__ float g_w[EE];
__device__ float g_sumsA[5][256];    // per-layer BN stats
__device__ float g_sumsqA[5][256];
__device__ float g_cvec[256];

__device__ __forceinline__ uint32_t smem_u32(const void* p) {
    uint32_t a;
    asm("{ .reg .u64 t; cvta.to.shared.u64 t, %1; cvt.u32.u64 %0, t; }" : "=r"(a) : "l"(p));
    return a;
}

// ================= preprocessing =================
__global__ void k_zero() {
    int i = blockIdx.x * blockDim.x + threadIdx.x;
    if (i < NN) g_deg[i] = 0;
    if (i < 5 * 256) {
        ((float*)g_sumsA)[i]  = 0.f;
        ((float*)g_sumsqA)[i] = 0.f;
    }
}
__global__ void k_hist(const int* __restrict__ dst) {
    int e = blockIdx.x * blockDim.x + threadIdx.x;
    if (e < EE) atomicAdd(&g_deg[dst[e]], 1);
}
__global__ void k_dis() {
    int i = blockIdx.x * blockDim.x + threadIdx.x;
    if (i < NN) {
        int in = g_deg[i];
        g_dis[i] = rsqrtf((float)(in + 1));   // self loop included
        g_cnt[i] = in;
    }
}
__global__ void k_scan1() {
    __shared__ int sh[512];
    int i = blockIdx.x * 512 + threadIdx.x;
    int v = (i < NN) ? g_cnt[i] : 0;
    sh[threadIdx.x] = v;
    __syncthreads();
    #pragma unroll
    for (int off = 1; off < 512; off <<= 1) {
        int t = (threadIdx.x >= off) ? sh[threadIdx.x - off] : 0;
        __syncthreads();
        sh[threadIdx.x] += t;
        __syncthreads();
    }
    if (i < NN) g_rowptr[i] = sh[threadIdx.x] - v;
    if (threadIdx.x == 511) g_blocksum[blockIdx.x] = sh[511];
}
__global__ void k_scan2(int nb) {
    __shared__ int sh[256];
    int v = (threadIdx.x < nb) ? g_blocksum[threadIdx.x] : 0;
    sh[threadIdx.x] = v;
    __syncthreads();
    #pragma unroll
    for (int off = 1; off < 256; off <<= 1) {
        int t = (threadIdx.x >= off) ? sh[threadIdx.x - off] : 0;
        __syncthreads();
        sh[threadIdx.x] += t;
        __syncthreads();
    }
    if (threadIdx.x < nb) g_blockoff[threadIdx.x] = sh[threadIdx.x] - v;
}
__global__ void k_scan3() {
    int i = blockIdx.x * 512 + threadIdx.x;
    if (i < NN) {
        int r = g_rowptr[i] + g_blockoff[blockIdx.x];
        g_rowptr[i] = r;
        g_cursor[i] = r;
    }
    if (i == 0 && blockIdx.x == 0) g_rowptr[NN] = EE;
}
__global__ void k_fill(const int* __restrict__ ei) {
    int e = blockIdx.x * blockDim.x + threadIdx.x;
    if (e < EE) {
        int s  = ei[e];
        int dv = ei[EE + e];
        float w = g_dis[s] * g_dis[dv];
        int p = atomicAdd(&g_cursor[dv], 1);
        g_src[p] = s;
        g_w[p]   = w;
    }
}

// ================= conversions / merged per-layer prep =================
__global__ void k_convX(const float* __restrict__ x) {
    int i = blockIdx.x;
    int k = threadIdx.x;
    float v = (k < 220) ? x[(size_t)i * 220 + k] : 0.f;
    g_actF[(size_t)i * 256 + k] = __float2half_rn(v);
}

__global__ void __launch_bounds__(256) k_prepLayer(
    const float* __restrict__ W, const float* __restrict__ gg, const float* __restrict__ bb,
    int K_, int N_, int KP, int useScale, int statIdx)
{
    __shared__ float s_scale[256], s_shift[256], s_red[256];
    int t = threadIdx.x;
    int n = blockIdx.x;

    float sc = 1.f, sh = 0.f;
    if (useScale && t < K_) {
        float m   = g_sumsA[statIdx][t] * (1.f / NN);
        float var = g_sumsqA[statIdx][t] * (1.f / NN) - m * m;
        float rs  = rsqrtf(var + EPSV);
        sc = rs * gg[t];
        sh = bb[t] - m * sc;
    }
    s_scale[t] = sc;
    s_shift[t] = sh;
    __syncthreads();

    for (int k = t; k < KP; k += 256) {
        float v = 0.f;
        if (n < N_ && k < K_) v = W[(size_t)k * N_ + n] * s_scale[k];
        __nv_bfloat16 hv = __float2bfloat16(v);
        g_hB[(size_t)n * KP + k] = hv;
        g_lB[(size_t)n * KP + k] = __float2bfloat16(v - __bfloat162float(hv));
    }

    if (useScale) {
        float part = 0.f;
        if (n < N_)
            for (int k = t; k < K_; k += 256) part += s_shift[k] * W[(size_t)k * N_ + n];
        s_red[t] = part;
        __syncthreads();
        #pragma unroll
        for (int off = 128; off > 0; off >>= 1) {
            if (t < off) s_red[t] += s_red[t + off];
            __syncthreads();
        }
        if (t == 0) g_cvec[n] = s_red[0];
    }
}

// ================= HMMA bf16 3-term split GEMM (fp16 act, on-the-fly split) ========
__device__ __forceinline__ void ldsm4(uint32_t& r0, uint32_t& r1, uint32_t& r2, uint32_t& r3,
                                      uint32_t addr) {
    asm volatile("ldmatrix.sync.aligned.m8n8.x4.shared.b16 {%0,%1,%2,%3}, [%4];"
        : "=r"(r0), "=r"(r1), "=r"(r2), "=r"(r3) : "r"(addr));
}
__device__ __forceinline__ void mma16816(float* d, uint32_t a0, uint32_t a1, uint32_t a2,
                                         uint32_t a3, uint32_t b0, uint32_t b1) {
    asm volatile(
        "mma.sync.aligned.m16n8k16.row.col.f32.bf16.bf16.f32 "
        "{%0,%1,%2,%3}, {%4,%5,%6,%7}, {%8,%9}, {%0,%1,%2,%3};"
        : "+f"(d[0]), "+f"(d[1]), "+f"(d[2]), "+f"(d[3])
        : "r"(a0), "r"(a1), "r"(a2), "r"(a3), "r"(b0), "r"(b1));
}
#define SWZ(r, q) (((uint32_t)(r) << 7) + ((((uint32_t)(q)) ^ ((uint32_t)(r) & 7)) << 4))

template <int JM8>
__global__ void __launch_bounds__(256, 2) k_hgemm(int KP, int strideOut, int useCvec,
                                                  int colOff, int outHalf) {
    constexpr int TMAX  = JM8 / 2;
    constexpr int BROWS = JM8 * 8;
    __shared__ __nv_bfloat16 sAh[128 * 64];
    __shared__ __nv_bfloat16 sAl[128 * 64];
    __shared__ __nv_bfloat16 sBh[64 * 64];
    __shared__ __nv_bfloat16 sBl[64 * 64];

    int tid = threadIdx.x;
    int warp = tid >> 5, lane = tid & 31;
    int rowbase = blockIdx.y * 128;
    int colbase = colOff + blockIdx.x * 64;

    float acc[JM8][4];
    #pragma unroll
    for (int j = 0; j < JM8; j++)
        #pragma unroll
        for (int q = 0; q < 4; q++) acc[j][q] = 0.f;

    uint32_t sAhB = smem_u32(sAh), sAlB = smem_u32(sAl);
    uint32_t sBhB = smem_u32(sBh), sBlB = smem_u32(sBl);

    int arow = warp * 16 + (lane & 15);
    int achk = lane >> 4;
    int brow = (lane & 7) + ((lane >> 4) << 3);
    int bchk = (lane >> 3) & 1;

    int nchunks = KP >> 6;
    for (int c = 0; c < nchunks; c++) {
        int k0 = c << 6;
        // A tile: fp16 load, exact bf16 hi/lo decomposition into smem
        #pragma unroll
        for (int it = 0; it < 4; it++) {
            int u = tid + it * 256;
            int r = u >> 3, q = u & 7;
            int gr = rowbase + r;
            uint4 vf = make_uint4(0u, 0u, 0u, 0u);
            if (gr < NN)
                vf = *(const uint4*)(g_actF + (size_t)gr * KP + k0 + q * 8);
            const __half2* hsrc = (const __half2*)&vf;
            uint4 vh, vl;
            __nv_bfloat16* hp = (__nv_bfloat16*)&vh;
            __nv_bfloat16* lp = (__nv_bfloat16*)&vl;
            #pragma unroll
            for (int i = 0; i < 4; i++) {
                float2 f = __half22float2(hsrc[i]);
                __nv_bfloat16 h0 = __float2bfloat16(f.x);
                __nv_bfloat16 h1 = __float2bfloat16(f.y);
                hp[2*i]   = h0;
                hp[2*i+1] = h1;
                lp[2*i]   = __float2bfloat16(f.x - __bfloat162float(h0));
                lp[2*i+1] = __float2bfloat16(f.y - __bfloat162float(h1));
            }
            uint32_t dz = SWZ(r, q);
            *(uint4*)((char*)sAh + dz) = vh;
            *(uint4*)((char*)sAl + dz) = vl;
        }
        #pragma unroll
        for (int it = 0; it < BROWS / 32; it++) {
            int u = tid + it * 256;
            int n = u >> 3, q = u & 7;
            size_t off = (size_t)(colbase + n) * KP + k0 + q * 8;
            uint32_t dz = SWZ(n, q);
            *(uint4*)((char*)sBh + dz) = *(const uint4*)(g_hB + off);
            *(uint4*)((char*)sBl + dz) = *(const uint4*)(g_lB + off);
        }
        __syncthreads();

        #pragma unroll
        for (int s = 0; s < 4; s++) {
            int aq = s * 2 + achk;
            uint32_t aoff = SWZ(arow, aq);
            uint32_t ah0, ah1, ah2, ah3, al0, al1, al2, al3;
            ldsm4(ah0, ah1, ah2, ah3, sAhB + aoff);
            ldsm4(al0, al1, al2, al3, sAlB + aoff);
            int bq = s * 2 + bchk;
            uint32_t bh[JM8 * 2], bl[JM8 * 2];
            #pragma unroll
            for (int t = 0; t < TMAX; t++) {
                uint32_t boff = SWZ(brow + t * 16, bq);
                ldsm4(bh[t*4], bh[t*4+1], bh[t*4+2], bh[t*4+3], sBhB + boff);
                ldsm4(bl[t*4], bl[t*4+1], bl[t*4+2], bl[t*4+3], sBlB + boff);
            }
            #pragma unroll
            for (int j = 0; j < JM8; j++) {
                mma16816(acc[j], ah0, ah1, ah2, ah3, bh[j*2], bh[j*2+1]);
                mma16816(acc[j], ah0, ah1, ah2, ah3, bl[j*2], bl[j*2+1]);
                mma16816(acc[j], al0, al1, al2, al3, bh[j*2], bh[j*2+1]);
            }
        }
        __syncthreads();
    }

    int r0 = rowbase + warp * 16 + (lane >> 2);
    int c00 = colbase + (lane & 3) * 2;
    #pragma unroll
    for (int j = 0; j < JM8; j++) {
        int col = c00 + j * 8;
        if (col >= strideOut) continue;
        float cv0 = useCvec ? g_cvec[col] : 0.f;
        float cv1 = useCvec ? g_cvec[col + 1] : 0.f;
        float v00 = acc[j][0] + cv0, v01 = acc[j][1] + cv1;
        float v10 = acc[j][2] + cv0, v11 = acc[j][3] + cv1;
        if (outHalf) {
            if (r0 < NN)
                *(__half2*)(g_bufH + (size_t)r0 * strideOut + col) = __floats2half2_rn(v00, v01);
            if (r0 + 8 < NN)
                *(__half2*)(g_bufH + (size_t)(r0 + 8) * strideOut + col) = __floats2half2_rn(v10, v11);
        } else {
            if (r0 < NN) {
                float* p = g_bufA + (size_t)r0 * strideOut + col;
                p[0] = v00; p[1] = v01;
            }
            if (r0 + 8 < NN) {
                float* p = g_bufA + (size_t)(r0 + 8) * strideOut + col;
                p[0] = v10; p[1] = v11;
            }
        }
    }
}

// ===== aggregation over fp16 h (layers 1-5): +bias, relu, fp16 act-out, BN stats ===
template <int EPG>
__global__ void __launch_bounds__(256) k_aggH(const float* __restrict__ bias,
                                              int d, int s8, int KPn, int statIdx)
{
    constexpr int G = 32 / EPG;
    int lane = threadIdx.x & 31;
    int warp = threadIdx.x >> 5;
    int sub  = lane & (G - 1);
    int grp  = lane / G;

    __shared__ float sh_sum[256], sh_sq[256], sh_bias[256];
    if (threadIdx.x < 256) {
        sh_sum[threadIdx.x] = 0.f;
        sh_sq[threadIdx.x] = 0.f;
        sh_bias[threadIdx.x] = (threadIdx.x < d) ? bias[threadIdx.x] : 0.f;
    }
    __syncthreads();

    float st_s[8], st_q[8];
    #pragma unroll
    for (int i = 0; i < 8; i++) { st_s[i] = 0.f; st_q[i] = 0.f; }

    const float4* __restrict__ H8 = (const float4*)g_bufH;
    bool lactive = (sub < s8);
    int nsg = KPn >> 3;

    for (int node = blockIdx.x * 8 + warp; node < NN; node += gridDim.x * 8) {
        float acc8[8];
        #pragma unroll
        for (int i = 0; i < 8; i++) acc8[i] = 0.f;

        float dn = g_dis[node];
        if (grp == 0 && lactive) {
            float sw = dn * dn;
            float4 v = H8[(size_t)node * s8 + sub];
            const __half2* h2 = reinterpret_cast<const __half2*>(&v);
            #pragma unroll
            for (int i = 0; i < 4; i++) {
                float2 t = __half22float2(h2[i]);
                acc8[2*i]   = sw * t.x;
                acc8[2*i+1] = sw * t.y;
            }
        }

        int start = g_rowptr[node], end = g_rowptr[node + 1];
        for (int base = start; base < end; base += 32) {
            int e = base + lane;
            int ssrc = 0; float ww = 0.f;
            if (e < end) { ssrc = g_src[e]; ww = g_w[e]; }
            int cnt = min(32, end - base);
            int steps = (cnt + EPG - 1) / EPG;
            for (int t = 0; t < steps; t++) {
                int ei = t * EPG + grp;
                int   s2 = __shfl_sync(0xffffffffu, ssrc, ei);
                float w2 = __shfl_sync(0xffffffffu, ww, ei);
                if (ei < cnt && lactive) {
                    float4 v = H8[(size_t)s2 * s8 + sub];
                    const __half2* h2 = reinterpret_cast<const __half2*>(&v);
                    #pragma unroll
                    for (int i = 0; i < 4; i++) {
                        float2 tt = __half22float2(h2[i]);
                        acc8[2*i]   += w2 * tt.x;
                        acc8[2*i+1] += w2 * tt.y;
                    }
                }
            }
        }

        if (EPG > 1) {
            #pragma unroll
            for (int off = G; off < 32; off <<= 1) {
                #pragma unroll
                for (int i = 0; i < 8; i++)
                    acc8[i] += __shfl_xor_sync(0xffffffffu, acc8[i], off);
            }
        }

        if (grp == 0) {
            for (int g = sub; g < nsg; g += G) {
                bool own = (g == sub);
                uint4 pf;
                __half* fp = (__half*)&pf;
                #pragma unroll
                for (int i = 0; i < 8; i++) {
                    int col = g * 8 + i;
                    float v = 0.f;
                    if (own && col < d) {
                        v = fmaxf(acc8[i] + sh_bias[col], 0.f);
                        st_s[i] += v;
                        st_q[i] += v * v;
                    }
                    fp[i] = __float2half_rn(v);
                }
                *(uint4*)(g_actF + (size_t)node * KPn + g * 8) = pf;
            }
        }
    }

    __syncthreads();
    if (grp == 0 && lactive) {
        #pragma unroll
        for (int i = 0; i < 8; i++) {
            int col = sub * 8 + i;
            if (col < d) {
                atomicAdd(&sh_sum[col], st_s[i]);
                atomicAdd(&sh_sq[col],  st_q[i]);
            }
        }
    }
    __syncthreads();
    if (threadIdx.x < d) {
        atomicAdd(&g_sumsA[statIdx][threadIdx.x],  sh_sum[threadIdx.x]);
        atomicAdd(&g_sumsqA[statIdx][threadIdx.x], sh_sq[threadIdx.x]);
    }
}

// ===== final aggregation (layer 6): fp32 gather, +bias, log_softmax =====
__global__ void __launch_bounds__(256) k_aggLast(const float* __restrict__ bias,
                                                 float* __restrict__ outp, int d, int s4)
{
    constexpr int EPG = 4, G = 8;
    int lane = threadIdx.x & 31;
    int warp = threadIdx.x >> 5;
    int sub  = lane & (G - 1);
    int grp  = lane / G;

    const float4* __restrict__ H = (const float4*)g_bufA;

    for (int node = blockIdx.x * 8 + warp; node < NN; node += gridDim.x * 8) {
        float4 acc = make_float4(0.f, 0.f, 0.f, 0.f);
        float dn = g_dis[node];
        if (grp == 0 && sub < s4) {
            float sw = dn * dn;
            float4 h = H[(size_t)node * s4 + sub];
            acc.x = sw * h.x; acc.y = sw * h.y; acc.z = sw * h.z; acc.w = sw * h.w;
        }

        int start = g_rowptr[node], end = g_rowptr[node + 1];
        for (int base = start; base < end; base += 32) {
            int e = base + lane;
            int ssrc = 0; float ww = 0.f;
            if (e < end) { ssrc = g_src[e]; ww = g_w[e]; }
            int cnt = min(32, end - base);
            int steps = (cnt + EPG - 1) / EPG;
            for (int t = 0; t < steps; t++) {
                int ei = t * EPG + grp;
                int   s2 = __shfl_sync(0xffffffffu, ssrc, ei);
                float w2 = __shfl_sync(0xffffffffu, ww, ei);
                if (ei < cnt && sub < s4) {
                    float4 h = H[(size_t)s2 * s4 + sub];
                    acc.x += w2 * h.x; acc.y += w2 * h.y;
                    acc.z += w2 * h.z; acc.w += w2 * h.w;
                }
            }
        }

        #pragma unroll
        for (int off = G; off < 32; off <<= 1) {
            acc.x += __shfl_xor_sync(0xffffffffu, acc.x, off);
            acc.y += __shfl_xor_sync(0xffffffffu, acc.y, off);
            acc.z += __shfl_xor_sync(0xffffffffu, acc.z, off);
            acc.w += __shfl_xor_sync(0xffffffffu, acc.w, off);
        }

        float vals[4] = {acc.x, acc.y, acc.z, acc.w};
        float lmax = -INFINITY;
        #pragma unroll
        for (int q = 0; q < 4; q++) {
            int col = sub * 4 + q;
            float v = (grp == 0 && col < d) ? vals[q] + bias[col] : -INFINITY;
            vals[q] = v;
            lmax = fmaxf(lmax, v);
        }
        #pragma unroll
        for (int off = 1; off < G; off <<= 1)
            lmax = fmaxf(lmax, __shfl_xor_sync(0xffffffffu, lmax, off));
        float lsum = 0.f;
        #pragma unroll
        for (int q = 0; q < 4; q++) {
            int col = sub * 4 + q;
            if (grp == 0 && col < d) lsum += expf(vals[q] - lmax);
        }
        #pragma unroll
        for (int off = 1; off < G; off <<= 1)
            lsum += __shfl_xor_sync(0xffffffffu, lsum, off);
        float lse = logf(lsum) + lmax;
        if (grp == 0) {
            #pragma unroll
            for (int q = 0; q < 4; q++) {
                int col = sub * 4 + q;
                if (col < d) outp[(size_t)node * d + col] = vals[q] - lse;
            }
        }
    }
}

// ================= launch =================
extern "C" void kernel_launch(void* const* d_in, const int* in_sizes, int n_in,
                              void* d_out, int out_size) {
    const float* x  = (const float*)d_in[0];
    const int*   ei = (const int*)d_in[1];
    static const int DIMS_[7]  = {220, 220, 150, 100, 60, 30, 17};
    static const int KPt[6]    = {256, 256, 192, 128, 64, 64};
    static const int NPADc[6]  = {224, 160, 128, 64, 32, 32};
    static const int STRIDEo[6]= {224, 152, 104, 64, 32, 20};
    const float* W[6]; const float* b[6];
    for (int i = 0; i < 6; i++) {
        W[i] = (const float*)d_in[2 + 2 * i];
        b[i] = (const float*)d_in[3 + 2 * i];
    }
    const float* gpar[5]; const float* bpar[5];
    for (int i = 0; i < 5; i++) {
        gpar[i] = (const float*)d_in[14 + 2 * i];
        bpar[i] = (const float*)d_in[15 + 2 * i];
    }

    // preprocessing
    k_zero<<<(NN + 255) / 256, 256>>>();
    k_hist<<<(EE + 255) / 256, 256>>>(ei + EE);
    k_dis<<<(NN + 255) / 256, 256>>>();
    int nb = (NN + 511) / 512;
    k_scan1<<<nb, 512>>>();
    k_scan2<<<1, 256>>>(nb);
    k_scan3<<<nb, 512>>>();
    k_fill<<<(EE + 255) / 256, 256>>>(ei);
    k_convX<<<NN, 256>>>(x);

    const int AGG_GRID = 1184;
    const int ROW_BLKS = (NN + 127) / 128;

    for (int L = 0; L < 6; L++) {
        int K_ = DIMS_[L], Nc = DIMS_[L + 1];
        int KP = KPt[L], Npad = NPADc[L], so = STRIDEo[L];
        int outHalf = (L < 5) ? 1 : 0;
        int uc = L > 0 ? 1 : 0;

        k_prepLayer<<<Npad, 256>>>(W[L],
                                   L > 0 ? gpar[L - 1] : nullptr,
                                   L > 0 ? bpar[L - 1] : nullptr,
                                   K_, Nc, KP, uc, L > 0 ? L - 1 : 0);

        int nfull = Npad / 64;
        int tail  = Npad - nfull * 64;
        if (nfull > 0) {
            dim3 gg(nfull, ROW_BLKS);
            k_hgemm<8><<<gg, 256>>>(KP, so, uc, 0, outHalf);
        }
        if (tail > 0) {
            dim3 gg(1, ROW_BLKS);
            k_hgemm<4><<<gg, 256>>>(KP, so, uc, nfull * 64, outHalf);
        }

        if (L < 5) {
            int s8 = so / 8;
            int KPn = KPt[L + 1];
            if (L <= 1)      k_aggH<1><<<AGG_GRID, 256>>>(b[L], Nc, s8, KPn, L);
            else if (L == 2) k_aggH<2><<<AGG_GRID, 256>>>(b[L], Nc, s8, KPn, L);
            else if (L == 3) k_aggH<4><<<AGG_GRID, 256>>>(b[L], Nc, s8, KPn, L);
            else             k_aggH<8><<<AGG_GRID, 256>>>(b[L], Nc, s8, KPn, L);
        } else {
            k_aggLast<<<AGG_GRID, 256>>>(b[L], (float*)d_out, Nc, so / 4);
        }
    }
}

// round 11
// speedup vs baseline: 2.2141x; 1.0272x over previous
#include <cuda_runtime.h>
#include <cuda_bf16.h>
#include <cuda_fp16.h>
#include <math.h>
#include <stdint.h>

#define NN 100000
#define EE 1600000
#define EPSV 1e-5f
#define LOSCALE 2048.0f
#define INV_LOSCALE (1.0f / 2048.0f)

// ================= device scratch =================
__device__ __half g_actF[(size_t)NN * 256];          // activation fp16, row stride KP
__device__ __half g_bufH[(size_t)NN * 224];          // GEMM output fp16 (layers 1-5), tight stride
__device__ float  g_bufA[(size_t)NN * 20];           // GEMM output fp32 (layer 6), stride 20
__device__ __half g_hB[57344];                       // W^T fp16 hi, [Npad, KP]
__device__ __half g_lB[57344];                       // W^T fp16 lo (scaled by 2048)
__device__ int   g_deg[NN];
__device__ float g_dis[NN];
__device__ int   g_rowptr[NN + 1];
__device__ int   g_cursor[NN];
__device__ int   g_blocksum[256];
__device__ int   g_blockoff[256];
__device__ int   g_src[EE];
__device__ float g_w[EE];
__device__ float g_sumsA[5][256];    // per-layer BN stats
__device__ float g_sumsqA[5][256];
__device__ float g_cvec[256];

__device__ __forceinline__ uint32_t smem_u32(const void* p) {
    uint32_t a;
    asm("{ .reg .u64 t; cvta.to.shared.u64 t, %1; cvt.u32.u64 %0, t; }" : "=r"(a) : "l"(p));
    return a;
}

// ================= preprocessing =================
__global__ void k_zero() {
    int i = blockIdx.x * blockDim.x + threadIdx.x;
    if (i < NN) g_deg[i] = 0;
    if (i < 5 * 256) {
        ((float*)g_sumsA)[i]  = 0.f;
        ((float*)g_sumsqA)[i] = 0.f;
    }
}
__global__ void k_hist(const int* __restrict__ dst) {
    int e = blockIdx.x * blockDim.x + threadIdx.x;
    if (e < EE) atomicAdd(&g_deg[dst[e]], 1);
}
__global__ void k_scan1() {
    __shared__ int sh[512];
    int i = blockIdx.x * 512 + threadIdx.x;
    int v = 0;
    if (i < NN) {
        v = g_deg[i];
        g_dis[i] = rsqrtf((float)(v + 1));   // self loop included
    }
    sh[threadIdx.x] = v;
    __syncthreads();
    #pragma unroll
    for (int off = 1; off < 512; off <<= 1) {
        int t = (threadIdx.x >= off) ? sh[threadIdx.x - off] : 0;
        __syncthreads();
        sh[threadIdx.x] += t;
        __syncthreads();
    }
    if (i < NN) g_rowptr[i] = sh[threadIdx.x] - v;
    if (threadIdx.x == 511) g_blocksum[blockIdx.x] = sh[511];
}
__global__ void k_scan2(int nb) {
    __shared__ int sh[256];
    int v = (threadIdx.x < nb) ? g_blocksum[threadIdx.x] : 0;
    sh[threadIdx.x] = v;
    __syncthreads();
    #pragma unroll
    for (int off = 1; off < 256; off <<= 1) {
        int t = (threadIdx.x >= off) ? sh[threadIdx.x - off] : 0;
        __syncthreads();
        sh[threadIdx.x] += t;
        __syncthreads();
    }
    if (threadIdx.x < nb) g_blockoff[threadIdx.x] = sh[threadIdx.x] - v;
}
__global__ void k_scan3() {
    int i = blockIdx.x * 512 + threadIdx.x;
    if (i < NN) {
        int r = g_rowptr[i] + g_blockoff[blockIdx.x];
        g_rowptr[i] = r;
        g_cursor[i] = r;
    }
    if (i == 0 && blockIdx.x == 0) g_rowptr[NN] = EE;
}
__global__ void k_fill(const int* __restrict__ ei) {
    int e = blockIdx.x * blockDim.x + threadIdx.x;
    if (e < EE) {
        int s  = ei[e];
        int dv = ei[EE + e];
        float w = g_dis[s] * g_dis[dv];
        int p = atomicAdd(&g_cursor[dv], 1);
        g_src[p] = s;
        g_w[p]   = w;
    }
}

// ================= conversions / merged per-layer prep =================
__global__ void k_convX(const float* __restrict__ x) {
    int i = blockIdx.x;
    int k = threadIdx.x;
    float v = (k < 220) ? x[(size_t)i * 220 + k] : 0.f;
    g_actF[(size_t)i * 256 + k] = __float2half_rn(v);
}

__global__ void __launch_bounds__(256) k_prepLayer(
    const float* __restrict__ W, const float* __restrict__ gg, const float* __restrict__ bb,
    int K_, int N_, int KP, int useScale, int statIdx)
{
    __shared__ float s_scale[256], s_shift[256], s_red[256];
    int t = threadIdx.x;
    int n = blockIdx.x;

    float sc = 1.f, sh = 0.f;
    if (useScale && t < K_) {
        float m   = g_sumsA[statIdx][t] * (1.f / NN);
        float var = g_sumsqA[statIdx][t] * (1.f / NN) - m * m;
        float rs  = rsqrtf(var + EPSV);
        sc = rs * gg[t];
        sh = bb[t] - m * sc;
    }
    s_scale[t] = sc;
    s_shift[t] = sh;
    __syncthreads();

    for (int k = t; k < KP; k += 256) {
        float v = 0.f;
        if (n < N_ && k < K_) v = W[(size_t)k * N_ + n] * s_scale[k];
        __half hv = __float2half_rn(v);
        g_hB[(size_t)n * KP + k] = hv;
        g_lB[(size_t)n * KP + k] = __float2half_rn((v - __half2float(hv)) * LOSCALE);
    }

    if (useScale) {
        float part = 0.f;
        if (n < N_)
            for (int k = t; k < K_; k += 256) part += s_shift[k] * W[(size_t)k * N_ + n];
        s_red[t] = part;
        __syncthreads();
        #pragma unroll
        for (int off = 128; off > 0; off >>= 1) {
            if (t < off) s_red[t] += s_red[t + off];
            __syncthreads();
        }
        if (t == 0) g_cvec[n] = s_red[0];
    }
}

// ================= HMMA fp16 2-term split GEMM ========
// D = A_fp16 @ (Bh + Bl/2048)^T, two accumulator sets combined in epilogue.
__device__ __forceinline__ void ldsm4(uint32_t& r0, uint32_t& r1, uint32_t& r2, uint32_t& r3,
                                      uint32_t addr) {
    asm volatile("ldmatrix.sync.aligned.m8n8.x4.shared.b16 {%0,%1,%2,%3}, [%4];"
        : "=r"(r0), "=r"(r1), "=r"(r2), "=r"(r3) : "r"(addr));
}
__device__ __forceinline__ void mma16816f(float* d, uint32_t a0, uint32_t a1, uint32_t a2,
                                          uint32_t a3, uint32_t b0, uint32_t b1) {
    asm volatile(
        "mma.sync.aligned.m16n8k16.row.col.f32.f16.f16.f32 "
        "{%0,%1,%2,%3}, {%4,%5,%6,%7}, {%8,%9}, {%0,%1,%2,%3};"
        : "+f"(d[0]), "+f"(d[1]), "+f"(d[2]), "+f"(d[3])
        : "r"(a0), "r"(a1), "r"(a2), "r"(a3), "r"(b0), "r"(b1));
}
#define SWZ(r, q) (((uint32_t)(r) << 7) + ((((uint32_t)(q)) ^ ((uint32_t)(r) & 7)) << 4))

template <int JM8>
__global__ void __launch_bounds__(256, 2) k_hgemm(int KP, int strideOut, int useCvec,
                                                  int colOff, int outHalf) {
    constexpr int TMAX  = JM8 / 2;
    constexpr int BROWS = JM8 * 8;
    __shared__ __half sA[128 * 64];
    __shared__ __half sBh[64 * 64];
    __shared__ __half sBl[64 * 64];

    int tid = threadIdx.x;
    int warp = tid >> 5, lane = tid & 31;
    int rowbase = blockIdx.y * 128;
    int colbase = colOff + blockIdx.x * 64;

    float accH[JM8][4], accL[JM8][4];
    #pragma unroll
    for (int j = 0; j < JM8; j++)
        #pragma unroll
        for (int q = 0; q < 4; q++) { accH[j][q] = 0.f; accL[j][q] = 0.f; }

    uint32_t sAB = smem_u32(sA);
    uint32_t sBhB = smem_u32(sBh), sBlB = smem_u32(sBl);

    int arow = warp * 16 + (lane & 15);
    int achk = lane >> 4;
    int brow = (lane & 7) + ((lane >> 4) << 3);
    int bchk = (lane >> 3) & 1;

    int nchunks = KP >> 6;
    for (int c = 0; c < nchunks; c++) {
        int k0 = c << 6;
        // A tile: straight fp16 copy (no conversion)
        #pragma unroll
        for (int it = 0; it < 4; it++) {
            int u = tid + it * 256;
            int r = u >> 3, q = u & 7;
            int gr = rowbase + r;
            uint4 vf = make_uint4(0u, 0u, 0u, 0u);
            if (gr < NN)
                vf = *(const uint4*)(g_actF + (size_t)gr * KP + k0 + q * 8);
            *(uint4*)((char*)sA + SWZ(r, q)) = vf;
        }
        // B tiles: fp16 hi/lo
        #pragma unroll
        for (int it = 0; it < BROWS / 32; it++) {
            int u = tid + it * 256;
            int n = u >> 3, q = u & 7;
            size_t off = (size_t)(colbase + n) * KP + k0 + q * 8;
            uint32_t dz = SWZ(n, q);
            *(uint4*)((char*)sBh + dz) = *(const uint4*)(g_hB + off);
            *(uint4*)((char*)sBl + dz) = *(const uint4*)(g_lB + off);
        }
        __syncthreads();

        #pragma unroll
        for (int s = 0; s < 4; s++) {
            int aq = s * 2 + achk;
            uint32_t ah0, ah1, ah2, ah3;
            ldsm4(ah0, ah1, ah2, ah3, sAB + SWZ(arow, aq));
            int bq = s * 2 + bchk;
            #pragma unroll
            for (int t = 0; t < TMAX; t++) {
                uint32_t bh[4], bl[4];
                uint32_t boff = SWZ(brow + t * 16, bq);
                ldsm4(bh[0], bh[1], bh[2], bh[3], sBhB + boff);
                ldsm4(bl[0], bl[1], bl[2], bl[3], sBlB + boff);
                #pragma unroll
                for (int jj = 0; jj < 2; jj++) {
                    int j = t * 2 + jj;
                    mma16816f(accH[j], ah0, ah1, ah2, ah3, bh[jj*2], bh[jj*2+1]);
                    mma16816f(accL[j], ah0, ah1, ah2, ah3, bl[jj*2], bl[jj*2+1]);
                }
            }
        }
        __syncthreads();
    }

    int r0 = rowbase + warp * 16 + (lane >> 2);
    int c00 = colbase + (lane & 3) * 2;
    #pragma unroll
    for (int j = 0; j < JM8; j++) {
        int col = c00 + j * 8;
        if (col >= strideOut) continue;
        float cv0 = useCvec ? g_cvec[col] : 0.f;
        float cv1 = useCvec ? g_cvec[col + 1] : 0.f;
        float v00 = accH[j][0] + accL[j][0] * INV_LOSCALE + cv0;
        float v01 = accH[j][1] + accL[j][1] * INV_LOSCALE + cv1;
        float v10 = accH[j][2] + accL[j][2] * INV_LOSCALE + cv0;
        float v11 = accH[j][3] + accL[j][3] * INV_LOSCALE + cv1;
        if (outHalf) {
            if (r0 < NN)
                *(__half2*)(g_bufH + (size_t)r0 * strideOut + col) = __floats2half2_rn(v00, v01);
            if (r0 + 8 < NN)
                *(__half2*)(g_bufH + (size_t)(r0 + 8) * strideOut + col) = __floats2half2_rn(v10, v11);
        } else {
            if (r0 < NN) {
                float* p = g_bufA + (size_t)r0 * strideOut + col;
                p[0] = v00; p[1] = v01;
            }
            if (r0 + 8 < NN) {
                float* p = g_bufA + (size_t)(r0 + 8) * strideOut + col;
                p[0] = v10; p[1] = v11;
            }
        }
    }
}

// ===== aggregation over fp16 h (layers 1-5): +bias, relu, fp16 act-out, BN stats ===
template <int EPG>
__global__ void __launch_bounds__(256) k_aggH(const float* __restrict__ bias,
                                              int d, int s8, int KPn, int statIdx)
{
    constexpr int G = 32 / EPG;
    int lane = threadIdx.x & 31;
    int warp = threadIdx.x >> 5;
    int sub  = lane & (G - 1);
    int grp  = lane / G;

    __shared__ float sh_sum[256], sh_sq[256], sh_bias[256];
    if (threadIdx.x < 256) {
        sh_sum[threadIdx.x] = 0.f;
        sh_sq[threadIdx.x] = 0.f;
        sh_bias[threadIdx.x] = (threadIdx.x < d) ? bias[threadIdx.x] : 0.f;
    }
    __syncthreads();

    float st_s[8], st_q[8];
    #pragma unroll
    for (int i = 0; i < 8; i++) { st_s[i] = 0.f; st_q[i] = 0.f; }

    const float4* __restrict__ H8 = (const float4*)g_bufH;
    bool lactive = (sub < s8);
    int nsg = KPn >> 3;

    for (int node = blockIdx.x * 8 + warp; node < NN; node += gridDim.x * 8) {
        float acc8[8];
        #pragma unroll
        for (int i = 0; i < 8; i++) acc8[i] = 0.f;

        float dn = g_dis[node];
        if (grp == 0 && lactive) {
            float sw = dn * dn;
            float4 v = H8[(size_t)node * s8 + sub];
            const __half2* h2 = reinterpret_cast<const __half2*>(&v);
            #pragma unroll
            for (int i = 0; i < 4; i++) {
                float2 t = __half22float2(h2[i]);
                acc8[2*i]   = sw * t.x;
                acc8[2*i+1] = sw * t.y;
            }
        }

        int start = g_rowptr[node], end = g_rowptr[node + 1];
        for (int base = start; base < end; base += 32) {
            int e = base + lane;
            int ssrc = 0; float ww = 0.f;
            if (e < end) { ssrc = g_src[e]; ww = g_w[e]; }
            int cnt = min(32, end - base);
            int steps = (cnt + EPG - 1) / EPG;
            for (int t = 0; t < steps; t++) {
                int ei = t * EPG + grp;
                int   s2 = __shfl_sync(0xffffffffu, ssrc, ei);
                float w2 = __shfl_sync(0xffffffffu, ww, ei);
                if (ei < cnt && lactive) {
                    float4 v = H8[(size_t)s2 * s8 + sub];
                    const __half2* h2 = reinterpret_cast<const __half2*>(&v);
                    #pragma unroll
                    for (int i = 0; i < 4; i++) {
                        float2 tt = __half22float2(h2[i]);
                        acc8[2*i]   += w2 * tt.x;
                        acc8[2*i+1] += w2 * tt.y;
                    }
                }
            }
        }

        if (EPG > 1) {
            #pragma unroll
            for (int off = G; off < 32; off <<= 1) {
                #pragma unroll
                for (int i = 0; i < 8; i++)
                    acc8[i] += __shfl_xor_sync(0xffffffffu, acc8[i], off);
            }
        }

        if (grp == 0) {
            for (int g = sub; g < nsg; g += G) {
                bool own = (g == sub);
                uint4 pf;
                __half* fp = (__half*)&pf;
                #pragma unroll
                for (int i = 0; i < 8; i++) {
                    int col = g * 8 + i;
                    float v = 0.f;
                    if (own && col < d) {
                        v = fmaxf(acc8[i] + sh_bias[col], 0.f);
                        st_s[i] += v;
                        st_q[i] += v * v;
                    }
                    fp[i] = __float2half_rn(v);
                }
                *(uint4*)(g_actF + (size_t)node * KPn + g * 8) = pf;
            }
        }
    }

    __syncthreads();
    if (grp == 0 && lactive) {
        #pragma unroll
        for (int i = 0; i < 8; i++) {
            int col = sub * 8 + i;
            if (col < d) {
                atomicAdd(&sh_sum[col], st_s[i]);
                atomicAdd(&sh_sq[col],  st_q[i]);
            }
        }
    }
    __syncthreads();
    if (threadIdx.x < d) {
        atomicAdd(&g_sumsA[statIdx][threadIdx.x],  sh_sum[threadIdx.x]);
        atomicAdd(&g_sumsqA[statIdx][threadIdx.x], sh_sq[threadIdx.x]);
    }
}

// ===== final aggregation (layer 6): fp32 gather, +bias, log_softmax =====
__global__ void __launch_bounds__(256) k_aggLast(const float* __restrict__ bias,
                                                 float* __restrict__ outp, int d, int s4)
{
    constexpr int EPG = 4, G = 8;
    int lane = threadIdx.x & 31;
    int warp = threadIdx.x >> 5;
    int sub  = lane & (G - 1);
    int grp  = lane / G;

    const float4* __restrict__ H = (const float4*)g_bufA;

    for (int node = blockIdx.x * 8 + warp; node < NN; node += gridDim.x * 8) {
        float4 acc = make_float4(0.f, 0.f, 0.f, 0.f);
        float dn = g_dis[node];
        if (grp == 0 && sub < s4) {
            float sw = dn * dn;
            float4 h = H[(size_t)node * s4 + sub];
            acc.x = sw * h.x; acc.y = sw * h.y; acc.z = sw * h.z; acc.w = sw * h.w;
        }

        int start = g_rowptr[node], end = g_rowptr[node + 1];
        for (int base = start; base < end; base += 32) {
            int e = base + lane;
            int ssrc = 0; float ww = 0.f;
            if (e < end) { ssrc = g_src[e]; ww = g_w[e]; }
            int cnt = min(32, end - base);
            int steps = (cnt + EPG - 1) / EPG;
            for (int t = 0; t < steps; t++) {
                int ei = t * EPG + grp;
                int   s2 = __shfl_sync(0xffffffffu, ssrc, ei);
                float w2 = __shfl_sync(0xffffffffu, ww, ei);
                if (ei < cnt && sub < s4) {
                    float4 h = H[(size_t)s2 * s4 + sub];
                    acc.x += w2 * h.x; acc.y += w2 * h.y;
                    acc.z += w2 * h.z; acc.w += w2 * h.w;
                }
            }
        }

        #pragma unroll
        for (int off = G; off < 32; off <<= 1) {
            acc.x += __shfl_xor_sync(0xffffffffu, acc.x, off);
            acc.y += __shfl_xor_sync(0xffffffffu, acc.y, off);
            acc.z += __shfl_xor_sync(0xffffffffu, acc.z, off);
            acc.w += __shfl_xor_sync(0xffffffffu, acc.w, off);
        }

        float vals[4] = {acc.x, acc.y, acc.z, acc.w};
        float lmax = -INFINITY;
        #pragma unroll
        for (int q = 0; q < 4; q++) {
            int col = sub * 4 + q;
            float v = (grp == 0 && col < d) ? vals[q] + bias[col] : -INFINITY;
            vals[q] = v;
            lmax = fmaxf(lmax, v);
        }
        #pragma unroll
        for (int off = 1; off < G; off <<= 1)
            lmax = fmaxf(lmax, __shfl_xor_sync(0xffffffffu, lmax, off));
        float lsum = 0.f;
        #pragma unroll
        for (int q = 0; q < 4; q++) {
            int col = sub * 4 + q;
            if (grp == 0 && col < d) lsum += expf(vals[q] - lmax);
        }
        #pragma unroll
        for (int off = 1; off < G; off <<= 1)
            lsum += __shfl_xor_sync(0xffffffffu, lsum, off);
        float lse = logf(lsum) + lmax;
        if (grp == 0) {
            #pragma unroll
            for (int q = 0; q < 4; q++) {
                int col = sub * 4 + q;
                if (col < d) outp[(size_t)node * d + col] = vals[q] - lse;
            }
        }
    }
}

// ================= launch =================
extern "C" void kernel_launch(void* const* d_in, const int* in_sizes, int n_in,
                              void* d_out, int out_size) {
    const float* x  = (const float*)d_in[0];
    const int*   ei = (const int*)d_in[1];
    static const int DIMS_[7]  = {220, 220, 150, 100, 60, 30, 17};
    static const int KPt[6]    = {256, 256, 192, 128, 64, 64};
    static const int NPADc[6]  = {224, 160, 128, 64, 32, 32};
    static const int STRIDEo[6]= {224, 152, 104, 64, 32, 20};
    const float* W[6]; const float* b[6];
    for (int i = 0; i < 6; i++) {
        W[i] = (const float*)d_in[2 + 2 * i];
        b[i] = (const float*)d_in[3 + 2 * i];
    }
    const float* gpar[5]; const float* bpar[5];
    for (int i = 0; i < 5; i++) {
        gpar[i] = (const float*)d_in[14 + 2 * i];
        bpar[i] = (const float*)d_in[15 + 2 * i];
    }

    // preprocessing
    k_zero<<<(NN + 255) / 256, 256>>>();
    k_hist<<<(EE + 255) / 256, 256>>>(ei + EE);
    int nb = (NN + 511) / 512;
    k_scan1<<<nb, 512>>>();
    k_scan2<<<1, 256>>>(nb);
    k_scan3<<<nb, 512>>>();
    k_fill<<<(EE + 255) / 256, 256>>>(ei);
    k_convX<<<NN, 256>>>(x);

    const int AGG_GRID = 1184;
    const int ROW_BLKS = (NN + 127) / 128;

    for (int L = 0; L < 6; L++) {
        int K_ = DIMS_[L], Nc = DIMS_[L + 1];
        int KP = KPt[L], Npad = NPADc[L], so = STRIDEo[L];
        int outHalf = (L < 5) ? 1 : 0;
        int uc = L > 0 ? 1 : 0;

        k_prepLayer<<<Npad, 256>>>(W[L],
                                   L > 0 ? gpar[L - 1] : nullptr,
                                   L > 0 ? bpar[L - 1] : nullptr,
                                   K_, Nc, KP, uc, L > 0 ? L - 1 : 0);

        int nfull = Npad / 64;
        int tail  = Npad - nfull * 64;
        if (nfull > 0) {
            dim3 gg(nfull, ROW_BLKS);
            k_hgemm<8><<<gg, 256>>>(KP, so, uc, 0, outHalf);
        }
        if (tail > 0) {
            dim3 gg(1, ROW_BLKS);
            k_hgemm<4><<<gg, 256>>>(KP, so, uc, nfull * 64, outHalf);
        }

        if (L < 5) {
            int s8 = so / 8;
            int KPn = KPt[L + 1];
            if (L <= 1)      k_aggH<1><<<AGG_GRID, 256>>>(b[L], Nc, s8, KPn, L);
            else if (L == 2) k_aggH<2><<<AGG_GRID, 256>>>(b[L], Nc, s8, KPn, L);
            else if (L == 3) k_aggH<4><<<AGG_GRID, 256>>>(b[L], Nc, s8, KPn, L);
            else             k_aggH<8><<<AGG_GRID, 256>>>(b[L], Nc, s8, KPn, L);
        } else {
            k_aggLast<<<AGG_GRID, 256>>>(b[L], (float*)d_out, Nc, so / 4);
        }
    }
}